// round 1
// baseline (speedup 1.0000x reference)
#include <cuda_runtime.h>
#include <math.h>

#define Hd      128
#define Ld      200
#define DTd     768
#define DId     512
#define Ed      8
#define NTOK    25600
#define TB      32
#define NTHREADS 256
#define KC      64
#define SW      132   // s_W row stride (k-major: s_W[k*SW + h])
#define SA      68    // gathered-A chunk row stride
#define SX      132   // persistent activation row stride

// shared memory layout (float offsets)
#define OFF_W   0                      // 64*132 = 8448
#define OFF_A   8448                   // 32*68  = 2176
#define OFF_X   10624                  // 32*132 = 4224
#define OFF_Y   14848
#define OFF_S   19072
#define OFF_GT  23296                  // 32*8
#define OFF_GI  23552
#define OFF_IDS 23808                  // 32 ints
#define SMEM_FLOATS 23840              // 95360 bytes

__device__ __forceinline__ float hreduce16(float v) {
    v += __shfl_xor_sync(0xffffffffu, v, 1);
    v += __shfl_xor_sync(0xffffffffu, v, 2);
    v += __shfl_xor_sync(0xffffffffu, v, 4);
    v += __shfl_xor_sync(0xffffffffu, v, 8);
    return v;
}

// Load a [128 x KC] weight chunk (row-major, leading dim ldw) into smem transposed:
// s_W[k*SW + h]. Coalesced float4 global reads, conflict-free smem writes (SW=132).
__device__ __forceinline__ void load_w_chunk(const float* __restrict__ Wg, int ldw, int kc,
                                             float* __restrict__ sW, int tid) {
#pragma unroll
    for (int j = 0; j < 8; ++j) {
        int idx = tid + j * NTHREADS;          // 0..2047 float4 slots
        int h   = idx >> 4;                    // 16 float4 per output row
        int k4  = (idx & 15) * 4;
        float4 v = *reinterpret_cast<const float4*>(Wg + (long)h * ldw + kc + k4);
        sW[(k4 + 0) * SW + h] = v.x;
        sW[(k4 + 1) * SW + h] = v.y;
        sW[(k4 + 2) * SW + h] = v.z;
        sW[(k4 + 3) * SW + h] = v.w;
    }
}

// One KC=64 GEMM chunk: 2 tokens x 8 outputs per thread.
__device__ __forceinline__ void gemm_chunk(const float* __restrict__ a0p,
                                           const float* __restrict__ a1p,
                                           const float* __restrict__ sW,
                                           int hb, float acc0[8], float acc1[8]) {
#pragma unroll 8
    for (int k = 0; k < KC; ++k) {
        float a0 = a0p[k];
        float a1 = a1p[k];
        const float* wp = sW + k * SW + hb;
        float4 b0 = *reinterpret_cast<const float4*>(wp);
        float4 b1 = *reinterpret_cast<const float4*>(wp + 4);
        float b[8] = {b0.x, b0.y, b0.z, b0.w, b1.x, b1.y, b1.z, b1.w};
#pragma unroll
        for (int j = 0; j < 8; ++j) {
            acc0[j] = fmaf(a0, b[j], acc0[j]);
            acc1[j] = fmaf(a1, b[j], acc1[j]);
        }
    }
}

// softmax over 8 -> keep top-2 (earliest index on ties, matching lax.top_k) -> renorm
__device__ __forceinline__ void route8(float* g) {
    float m = g[0];
#pragma unroll
    for (int e = 1; e < Ed; ++e) m = fmaxf(m, g[e]);
    float ex[Ed]; float s = 0.f;
#pragma unroll
    for (int e = 0; e < Ed; ++e) { ex[e] = __expf(g[e] - m); s += ex[e]; }
    float inv = 1.f / s;
#pragma unroll
    for (int e = 0; e < Ed; ++e) ex[e] *= inv;
    int i1 = 0; float w1 = ex[0];
#pragma unroll
    for (int e = 1; e < Ed; ++e) if (ex[e] > w1) { w1 = ex[e]; i1 = e; }
    int i2 = -1; float w2 = -1.f;
#pragma unroll
    for (int e = 0; e < Ed; ++e) if (e != i1 && ex[e] > w2) { w2 = ex[e]; i2 = e; }
    float den = 1.f / (w1 + w2 + 1e-8f);
#pragma unroll
    for (int e = 0; e < Ed; ++e)
        g[e] = (e == i1) ? w1 * den : ((e == i2) ? w2 * den : 0.f);
}

__global__ __launch_bounds__(NTHREADS, 2)
void sasrec_fused_kernel(
    const int*   __restrict__ input_ids,
    const float* __restrict__ t_noise,   const float* __restrict__ i_noise,
    const float* __restrict__ item_table,const float* __restrict__ pos_table,
    const float* __restrict__ text_table,const float* __restrict__ img_table,
    const float* __restrict__ fc_text_w, const float* __restrict__ fc_text_b,
    const float* __restrict__ fc_img_w,  const float* __restrict__ fc_img_b,
    const float* __restrict__ ln_w,      const float* __restrict__ ln_b,
    const float* __restrict__ mu_t_w,    const float* __restrict__ mu_t_b,
    const float* __restrict__ sg_t_w,    const float* __restrict__ sg_t_b,
    const float* __restrict__ mu_i_w,    const float* __restrict__ mu_i_b,
    const float* __restrict__ sg_i_w,    const float* __restrict__ sg_i_b,
    const float* __restrict__ gate_w,    const float* __restrict__ gate_b,
    const float* __restrict__ texp_w,    const float* __restrict__ texp_b,
    const float* __restrict__ iexp_w,    const float* __restrict__ iexp_b,
    const float* __restrict__ fus_w,     const float* __restrict__ fus_b,
    const float* __restrict__ fus_ln_w,  const float* __restrict__ fus_ln_b,
    float*       __restrict__ out)
{
    extern __shared__ float sm[];
    float* sW  = sm + OFF_W;
    float* sA  = sm + OFF_A;
    float* sX  = sm + OFF_X;
    float* sY  = sm + OFF_Y;
    float* sS  = sm + OFF_S;
    float* sgt = sm + OFF_GT;
    float* sgi = sm + OFF_GI;
    int*   sids = (int*)(sm + OFF_IDS);

    const int tid = threadIdx.x;
    const int tx  = tid & 15;
    const int ty  = tid >> 4;
    const int hb  = tx * 8;
    const int t0  = ty, t1 = ty + 16;
    const int n0  = blockIdx.x * TB;

    if (tid < TB) sids[tid] = input_ids[n0 + tid];
    __syncthreads();

    // ---------------- stage 0: seq_emb = LN(item_emb + pos_emb) -> sS ----------------
    {
#pragma unroll
        for (int p = 0; p < 2; ++p) {
            int t  = (p == 0) ? t0 : t1;
            int n  = n0 + t;
            int id = sids[t];
            int pos = n % Ld;
            float v[8]; float s = 0.f, sq = 0.f;
#pragma unroll
            for (int j = 0; j < 8; ++j) {
                int h = hb + j;
                float x = item_table[(long)id * Hd + h] + pos_table[pos * Hd + h];
                v[j] = x; s += x; sq += x * x;
            }
            s  = hreduce16(s);
            sq = hreduce16(sq);
            float mean = s * (1.f / Hd);
            float var  = sq * (1.f / Hd) - mean * mean;
            float inv  = rsqrtf(var + 1e-12f);
#pragma unroll
            for (int j = 0; j < 8; ++j) {
                int h = hb + j;
                sS[t * SX + h] = (v[j] - mean) * inv * ln_w[h] + ln_b[h];
            }
        }
    }

    float acc0[8], acc1[8];

    // ---------------- stage 1: text_emb = l2norm(text_table[ids] @ fc_text_w^T + b) -> sX
    {
#pragma unroll
        for (int j = 0; j < 8; ++j) { acc0[j] = 0.f; acc1[j] = 0.f; }
        for (int kc = 0; kc < DTd; kc += KC) {
            __syncthreads();
#pragma unroll
            for (int j = 0; j < 2; ++j) {      // gather A chunk [32][64]
                int idx = tid + j * NTHREADS;  // 0..511 float4 slots
                int t = idx >> 4, kq = idx & 15;
                float4 v = *reinterpret_cast<const float4*>(
                    text_table + (long)sids[t] * DTd + kc + kq * 4);
                *reinterpret_cast<float4*>(sA + t * SA + kq * 4) = v;
            }
            load_w_chunk(fc_text_w, DTd, kc, sW, tid);
            __syncthreads();
            gemm_chunk(sA + t0 * SA, sA + t1 * SA, sW, hb, acc0, acc1);
        }
        float ss0 = 0.f, ss1 = 0.f;
#pragma unroll
        for (int j = 0; j < 8; ++j) {
            float b = fc_text_b[hb + j];
            acc0[j] += b; acc1[j] += b;
            ss0 += acc0[j] * acc0[j]; ss1 += acc1[j] * acc1[j];
        }
        ss0 = hreduce16(ss0); ss1 = hreduce16(ss1);
        float sc0 = 1.f / fmaxf(sqrtf(ss0), 1e-12f);
        float sc1 = 1.f / fmaxf(sqrtf(ss1), 1e-12f);
#pragma unroll
        for (int j = 0; j < 8; ++j) {
            sX[t0 * SX + hb + j] = acc0[j] * sc0;
            sX[t1 * SX + hb + j] = acc1[j] * sc1;
        }
    }

    // ---------------- stage 2: img_emb -> sY ----------------
    {
#pragma unroll
        for (int j = 0; j < 8; ++j) { acc0[j] = 0.f; acc1[j] = 0.f; }
        for (int kc = 0; kc < DId; kc += KC) {
            __syncthreads();
#pragma unroll
            for (int j = 0; j < 2; ++j) {
                int idx = tid + j * NTHREADS;
                int t = idx >> 4, kq = idx & 15;
                float4 v = *reinterpret_cast<const float4*>(
                    img_table + (long)sids[t] * DId + kc + kq * 4);
                *reinterpret_cast<float4*>(sA + t * SA + kq * 4) = v;
            }
            load_w_chunk(fc_img_w, DId, kc, sW, tid);
            __syncthreads();
            gemm_chunk(sA + t0 * SA, sA + t1 * SA, sW, hb, acc0, acc1);
        }
        float ss0 = 0.f, ss1 = 0.f;
#pragma unroll
        for (int j = 0; j < 8; ++j) {
            float b = fc_img_b[hb + j];
            acc0[j] += b; acc1[j] += b;
            ss0 += acc0[j] * acc0[j]; ss1 += acc1[j] * acc1[j];
        }
        ss0 = hreduce16(ss0); ss1 = hreduce16(ss1);
        float sc0 = 1.f / fmaxf(sqrtf(ss0), 1e-12f);
        float sc1 = 1.f / fmaxf(sqrtf(ss1), 1e-12f);
#pragma unroll
        for (int j = 0; j < 8; ++j) {
            sY[t0 * SX + hb + j] = acc0[j] * sc0;
            sY[t1 * SX + hb + j] = acc1[j] * sc1;
        }
    }

    // ---------------- stage 3: VAE reparam text: t_z = mu + exp(sg)*noise -> sX ----------------
    {
        float mu0[8], mu1[8];
#pragma unroll
        for (int j = 0; j < 8; ++j) { acc0[j] = 0.f; acc1[j] = 0.f; }
        for (int kc = 0; kc < Hd; kc += KC) {
            __syncthreads();
            load_w_chunk(mu_t_w, Hd, kc, sW, tid);
            __syncthreads();
            gemm_chunk(sX + t0 * SX + kc, sX + t1 * SX + kc, sW, hb, acc0, acc1);
        }
#pragma unroll
        for (int j = 0; j < 8; ++j) { mu0[j] = acc0[j]; mu1[j] = acc1[j]; acc0[j] = 0.f; acc1[j] = 0.f; }
        for (int kc = 0; kc < Hd; kc += KC) {
            __syncthreads();
            load_w_chunk(sg_t_w, Hd, kc, sW, tid);
            __syncthreads();
            gemm_chunk(sX + t0 * SX + kc, sX + t1 * SX + kc, sW, hb, acc0, acc1);
        }
        __syncthreads();   // everyone done reading sX
#pragma unroll
        for (int j = 0; j < 8; ++j) {
            int h = hb + j;
            float z0 = mu0[j] + mu_t_b[h] + __expf(acc0[j] + sg_t_b[h]) * t_noise[(long)(n0 + t0) * Hd + h];
            float z1 = mu1[j] + mu_t_b[h] + __expf(acc1[j] + sg_t_b[h]) * t_noise[(long)(n0 + t1) * Hd + h];
            sX[t0 * SX + h] = z0;
            sX[t1 * SX + h] = z1;
        }
    }

    // ---------------- stage 4: VAE reparam img -> sY ----------------
    {
        float mu0[8], mu1[8];
#pragma unroll
        for (int j = 0; j < 8; ++j) { acc0[j] = 0.f; acc1[j] = 0.f; }
        for (int kc = 0; kc < Hd; kc += KC) {
            __syncthreads();
            load_w_chunk(mu_i_w, Hd, kc, sW, tid);
            __syncthreads();
            gemm_chunk(sY + t0 * SX + kc, sY + t1 * SX + kc, sW, hb, acc0, acc1);
        }
#pragma unroll
        for (int j = 0; j < 8; ++j) { mu0[j] = acc0[j]; mu1[j] = acc1[j]; acc0[j] = 0.f; acc1[j] = 0.f; }
        for (int kc = 0; kc < Hd; kc += KC) {
            __syncthreads();
            load_w_chunk(sg_i_w, Hd, kc, sW, tid);
            __syncthreads();
            gemm_chunk(sY + t0 * SX + kc, sY + t1 * SX + kc, sW, hb, acc0, acc1);
        }
        __syncthreads();
#pragma unroll
        for (int j = 0; j < 8; ++j) {
            int h = hb + j;
            float z0 = mu0[j] + mu_i_b[h] + __expf(acc0[j] + sg_i_b[h]) * i_noise[(long)(n0 + t0) * Hd + h];
            float z1 = mu1[j] + mu_i_b[h] + __expf(acc1[j] + sg_i_b[h]) * i_noise[(long)(n0 + t1) * Hd + h];
            sY[t0 * SX + h] = z0;
            sY[t1 * SX + h] = z1;
        }
    }

    // ---------------- stage 5: gating (both modalities) ----------------
    __syncthreads();
    {
        int t = tid >> 3;          // 0..31
        int e = tid & 7;
        const float* gw = gate_w + e * Hd;
        float dt = 0.f, di = 0.f;
        for (int k = 0; k < Hd; ++k) {
            float w = gw[k];
            dt = fmaf(sX[t * SX + k], w, dt);
            di = fmaf(sY[t * SX + k], w, di);
        }
        sgt[t * Ed + e] = dt + gate_b[e];
        sgi[t * Ed + e] = di + gate_b[e];
    }
    __syncthreads();
    if (tid < TB) {
        route8(sgt + tid * Ed);
        route8(sgi + tid * Ed);
    }
    __syncthreads();

    // ---------------- stage 6: text experts (dense, gate-weighted) -> sX ----------------
    {
        float out0[8], out1[8];
#pragma unroll
        for (int j = 0; j < 8; ++j) { out0[j] = 0.f; out1[j] = 0.f; }
        for (int e = 0; e < Ed; ++e) {
#pragma unroll
            for (int j = 0; j < 8; ++j) { acc0[j] = 0.f; acc1[j] = 0.f; }
            const float* We = texp_w + (long)e * Hd * Hd;
            for (int kc = 0; kc < Hd; kc += KC) {
                __syncthreads();
                load_w_chunk(We, Hd, kc, sW, tid);
                __syncthreads();
                gemm_chunk(sX + t0 * SX + kc, sX + t1 * SX + kc, sW, hb, acc0, acc1);
            }
            float g0 = sgt[t0 * Ed + e];
            float g1 = sgt[t1 * Ed + e];
#pragma unroll
            for (int j = 0; j < 8; ++j) {
                float b = texp_b[e * Hd + hb + j];
                out0[j] = fmaf(g0, acc0[j] + b, out0[j]);
                out1[j] = fmaf(g1, acc1[j] + b, out1[j]);
            }
        }
        __syncthreads();
#pragma unroll
        for (int j = 0; j < 8; ++j) {
            sX[t0 * SX + hb + j] = out0[j];
            sX[t1 * SX + hb + j] = out1[j];
        }
    }

    // ---------------- stage 7: img experts -> sY ----------------
    {
        float out0[8], out1[8];
#pragma unroll
        for (int j = 0; j < 8; ++j) { out0[j] = 0.f; out1[j] = 0.f; }
        for (int e = 0; e < Ed; ++e) {
#pragma unroll
            for (int j = 0; j < 8; ++j) { acc0[j] = 0.f; acc1[j] = 0.f; }
            const float* We = iexp_w + (long)e * Hd * Hd;
            for (int kc = 0; kc < Hd; kc += KC) {
                __syncthreads();
                load_w_chunk(We, Hd, kc, sW, tid);
                __syncthreads();
                gemm_chunk(sY + t0 * SX + kc, sY + t1 * SX + kc, sW, hb, acc0, acc1);
            }
            float g0 = sgi[t0 * Ed + e];
            float g1 = sgi[t1 * Ed + e];
#pragma unroll
            for (int j = 0; j < 8; ++j) {
                float b = iexp_b[e * Hd + hb + j];
                out0[j] = fmaf(g0, acc0[j] + b, out0[j]);
                out1[j] = fmaf(g1, acc1[j] + b, out1[j]);
            }
        }
        __syncthreads();
#pragma unroll
        for (int j = 0; j < 8; ++j) {
            sY[t0 * SX + hb + j] = out0[j];
            sY[t1 * SX + hb + j] = out1[j];
        }
    }

    // ---------------- stage 8: fusion = seq + relu(LN(cat(t,i) @ fus_w^T + b)) ----------------
    {
#pragma unroll
        for (int j = 0; j < 8; ++j) { acc0[j] = 0.f; acc1[j] = 0.f; }
        for (int kc = 0; kc < 2 * Hd; kc += KC) {
            __syncthreads();
            load_w_chunk(fus_w, 2 * Hd, kc, sW, tid);
            __syncthreads();
            const float* a0 = (kc < Hd) ? (sX + t0 * SX + kc) : (sY + t0 * SX + (kc - Hd));
            const float* a1 = (kc < Hd) ? (sX + t1 * SX + kc) : (sY + t1 * SX + (kc - Hd));
            gemm_chunk(a0, a1, sW, hb, acc0, acc1);
        }
#pragma unroll
        for (int p = 0; p < 2; ++p) {
            float* acc = (p == 0) ? acc0 : acc1;
            int t = (p == 0) ? t0 : t1;
            float s = 0.f, sq = 0.f;
#pragma unroll
            for (int j = 0; j < 8; ++j) {
                acc[j] += fus_b[hb + j];
                s += acc[j]; sq += acc[j] * acc[j];
            }
            s  = hreduce16(s);
            sq = hreduce16(sq);
            float mean = s * (1.f / Hd);
            float var  = sq * (1.f / Hd) - mean * mean;
            float inv  = rsqrtf(var + 1e-5f);
            long n = n0 + t;
#pragma unroll
            for (int j = 0; j < 8; ++j) {
                int h = hb + j;
                float y = (acc[j] - mean) * inv * fus_ln_w[h] + fus_ln_b[h];
                out[n * Hd + h] = fmaxf(y, 0.f) + sS[t * SX + h];
            }
        }
    }
}

extern "C" void kernel_launch(void* const* d_in, const int* in_sizes, int n_in,
                              void* d_out, int out_size) {
    (void)in_sizes; (void)n_in; (void)out_size;
    const int*   input_ids  = (const int*)  d_in[0];
    const float* t_noise    = (const float*)d_in[1];
    const float* i_noise    = (const float*)d_in[2];
    const float* item_table = (const float*)d_in[3];
    const float* pos_table  = (const float*)d_in[4];
    const float* text_table = (const float*)d_in[5];
    const float* img_table  = (const float*)d_in[6];
    const float* fc_text_w  = (const float*)d_in[7];
    const float* fc_text_b  = (const float*)d_in[8];
    const float* fc_img_w   = (const float*)d_in[9];
    const float* fc_img_b   = (const float*)d_in[10];
    const float* ln_w       = (const float*)d_in[11];
    const float* ln_b       = (const float*)d_in[12];
    const float* mu_t_w     = (const float*)d_in[13];
    const float* mu_t_b     = (const float*)d_in[14];
    const float* sg_t_w     = (const float*)d_in[15];
    const float* sg_t_b     = (const float*)d_in[16];
    const float* mu_i_w     = (const float*)d_in[17];
    const float* mu_i_b     = (const float*)d_in[18];
    const float* sg_i_w     = (const float*)d_in[19];
    const float* sg_i_b     = (const float*)d_in[20];
    const float* gate_w     = (const float*)d_in[21];
    const float* gate_b     = (const float*)d_in[22];
    const float* texp_w     = (const float*)d_in[23];
    const float* texp_b     = (const float*)d_in[24];
    const float* iexp_w     = (const float*)d_in[25];
    const float* iexp_b     = (const float*)d_in[26];
    const float* fus_w      = (const float*)d_in[27];
    const float* fus_b      = (const float*)d_in[28];
    const float* fus_ln_w   = (const float*)d_in[29];
    const float* fus_ln_b   = (const float*)d_in[30];

    size_t smem = SMEM_FLOATS * sizeof(float);
    cudaFuncSetAttribute(sasrec_fused_kernel,
                         cudaFuncAttributeMaxDynamicSharedMemorySize, (int)smem);

    sasrec_fused_kernel<<<NTOK / TB, NTHREADS, smem>>>(
        input_ids, t_noise, i_noise, item_table, pos_table, text_table, img_table,
        fc_text_w, fc_text_b, fc_img_w, fc_img_b, ln_w, ln_b,
        mu_t_w, mu_t_b, sg_t_w, sg_t_b, mu_i_w, mu_i_b, sg_i_w, sg_i_b,
        gate_w, gate_b, texp_w, texp_b, iexp_w, iexp_b,
        fus_w, fus_b, fus_ln_w, fus_ln_b,
        (float*)d_out);
}

// round 2
// speedup vs baseline: 1.6224x; 1.6224x over previous
#include <cuda_runtime.h>
#include <math.h>

#define Hd      128
#define Ld      200
#define DTd     768
#define DId     512
#define Ed      8
#define NTOK    25600
#define TB      64
#define NTHREADS 256
#define KC      64
#define SW      132   // s_W row stride (k-major: s_W[k*SW + h])
#define SA      68    // gathered-A chunk row stride
#define SX      132   // persistent activation row stride

// shared memory layout (float offsets)
#define OFF_W   0                      // 64*132 = 8448
#define OFF_A   8448                   // 64*68  = 4352
#define OFF_X   12800                  // 64*132 = 8448
#define OFF_Y   21248
#define OFF_S   29696
#define OFF_GT  38144                  // 64*8 = 512
#define OFF_GI  38656                  // 512
#define OFF_IDS 39168                  // 64 ints
#define SMEM_FLOATS 39232              // 156,928 bytes

__device__ __forceinline__ float hreduce16(float v) {
    v += __shfl_xor_sync(0xffffffffu, v, 1);
    v += __shfl_xor_sync(0xffffffffu, v, 2);
    v += __shfl_xor_sync(0xffffffffu, v, 4);
    v += __shfl_xor_sync(0xffffffffu, v, 8);
    return v;
}

// Load a [128 x KC] weight chunk (row-major, leading dim ldw) into smem transposed:
// s_W[k*SW + h]. Coalesced float4 global reads, conflict-free smem writes.
__device__ __forceinline__ void load_w_chunk(const float* __restrict__ Wg, int ldw, int kc,
                                             float* __restrict__ sW, int tid) {
#pragma unroll
    for (int j = 0; j < 8; ++j) {
        int idx = tid + j * NTHREADS;          // 0..2047 float4 slots
        int h   = idx >> 4;                    // 16 float4 per output row
        int k4  = (idx & 15) * 4;
        float4 v = *reinterpret_cast<const float4*>(Wg + (long)h * ldw + kc + k4);
        sW[(k4 + 0) * SW + h] = v.x;
        sW[(k4 + 1) * SW + h] = v.y;
        sW[(k4 + 2) * SW + h] = v.z;
        sW[(k4 + 3) * SW + h] = v.w;
    }
}

// One KC=64 GEMM chunk: 4 tokens x 8 outputs per thread.
__device__ __forceinline__ void gemm_chunk4(const float* __restrict__ a0,
                                            const float* __restrict__ a1,
                                            const float* __restrict__ a2,
                                            const float* __restrict__ a3,
                                            const float* __restrict__ sW,
                                            int hb, float acc[4][8]) {
#pragma unroll 4
    for (int k = 0; k < KC; ++k) {
        const float* wp = sW + k * SW + hb;
        float4 b0 = *reinterpret_cast<const float4*>(wp);
        float4 b1 = *reinterpret_cast<const float4*>(wp + 4);
        float b[8] = {b0.x, b0.y, b0.z, b0.w, b1.x, b1.y, b1.z, b1.w};
        float av[4] = {a0[k], a1[k], a2[k], a3[k]};
#pragma unroll
        for (int p = 0; p < 4; ++p)
#pragma unroll
            for (int j = 0; j < 8; ++j)
                acc[p][j] = fmaf(av[p], b[j], acc[p][j]);
    }
}

// Single-token KC chunk (used in sparse expert stage).
__device__ __forceinline__ void gemm_chunk1(const float* __restrict__ a,
                                            const float* __restrict__ sW,
                                            int hb, float acc[8]) {
#pragma unroll 4
    for (int k = 0; k < KC; ++k) {
        const float* wp = sW + k * SW + hb;
        float4 b0 = *reinterpret_cast<const float4*>(wp);
        float4 b1 = *reinterpret_cast<const float4*>(wp + 4);
        float av = a[k];
        acc[0] = fmaf(av, b0.x, acc[0]);
        acc[1] = fmaf(av, b0.y, acc[1]);
        acc[2] = fmaf(av, b0.z, acc[2]);
        acc[3] = fmaf(av, b0.w, acc[3]);
        acc[4] = fmaf(av, b1.x, acc[4]);
        acc[5] = fmaf(av, b1.y, acc[5]);
        acc[6] = fmaf(av, b1.z, acc[6]);
        acc[7] = fmaf(av, b1.w, acc[7]);
    }
}

// softmax over 8 -> keep top-2 (earliest index on ties) -> renorm
__device__ __forceinline__ void route8(float* g) {
    float m = g[0];
#pragma unroll
    for (int e = 1; e < Ed; ++e) m = fmaxf(m, g[e]);
    float ex[Ed]; float s = 0.f;
#pragma unroll
    for (int e = 0; e < Ed; ++e) { ex[e] = __expf(g[e] - m); s += ex[e]; }
    float inv = 1.f / s;
#pragma unroll
    for (int e = 0; e < Ed; ++e) ex[e] *= inv;
    int i1 = 0; float w1 = ex[0];
#pragma unroll
    for (int e = 1; e < Ed; ++e) if (ex[e] > w1) { w1 = ex[e]; i1 = e; }
    int i2 = -1; float w2 = -1.f;
#pragma unroll
    for (int e = 0; e < Ed; ++e) if (e != i1 && ex[e] > w2) { w2 = ex[e]; i2 = e; }
    float den = 1.f / (w1 + w2 + 1e-8f);
#pragma unroll
    for (int e = 0; e < Ed; ++e)
        g[e] = (e == i1) ? w1 * den : ((e == i2) ? w2 * den : 0.f);
}

__global__ __launch_bounds__(NTHREADS, 1)
void sasrec_fused_kernel(
    const int*   __restrict__ input_ids,
    const float* __restrict__ t_noise,   const float* __restrict__ i_noise,
    const float* __restrict__ item_table,const float* __restrict__ pos_table,
    const float* __restrict__ text_table,const float* __restrict__ img_table,
    const float* __restrict__ fc_text_w, const float* __restrict__ fc_text_b,
    const float* __restrict__ fc_img_w,  const float* __restrict__ fc_img_b,
    const float* __restrict__ ln_w,      const float* __restrict__ ln_b,
    const float* __restrict__ mu_t_w,    const float* __restrict__ mu_t_b,
    const float* __restrict__ sg_t_w,    const float* __restrict__ sg_t_b,
    const float* __restrict__ mu_i_w,    const float* __restrict__ mu_i_b,
    const float* __restrict__ sg_i_w,    const float* __restrict__ sg_i_b,
    const float* __restrict__ gate_w,    const float* __restrict__ gate_b,
    const float* __restrict__ texp_w,    const float* __restrict__ texp_b,
    const float* __restrict__ iexp_w,    const float* __restrict__ iexp_b,
    const float* __restrict__ fus_w,     const float* __restrict__ fus_b,
    const float* __restrict__ fus_ln_w,  const float* __restrict__ fus_ln_b,
    float*       __restrict__ out)
{
    extern __shared__ float sm[];
    float* sW  = sm + OFF_W;
    float* sA  = sm + OFF_A;
    float* sX  = sm + OFF_X;
    float* sY  = sm + OFF_Y;
    float* sS  = sm + OFF_S;
    float* sgt = sm + OFF_GT;
    float* sgi = sm + OFF_GI;
    int*   sids = (int*)(sm + OFF_IDS);

    const int tid = threadIdx.x;
    const int tx  = tid & 15;
    const int ty  = tid >> 4;          // 0..15
    const int hb  = tx * 8;
    const int n0  = blockIdx.x * TB;
    // tokens handled by this thread: ty + 16*p, p = 0..3

    if (tid < TB) sids[tid] = input_ids[n0 + tid];
    __syncthreads();

    // ---------------- stage 0: seq_emb = LN(item_emb + pos_emb) -> sS ----------------
    {
#pragma unroll
        for (int p = 0; p < 4; ++p) {
            int t  = ty + 16 * p;
            int n  = n0 + t;
            int id = sids[t];
            int pos = n % Ld;
            float v[8]; float s = 0.f, sq = 0.f;
#pragma unroll
            for (int j = 0; j < 8; ++j) {
                int h = hb + j;
                float x = item_table[(long)id * Hd + h] + pos_table[pos * Hd + h];
                v[j] = x; s += x; sq += x * x;
            }
            s  = hreduce16(s);
            sq = hreduce16(sq);
            float mean = s * (1.f / Hd);
            float var  = sq * (1.f / Hd) - mean * mean;
            float inv  = rsqrtf(var + 1e-12f);
#pragma unroll
            for (int j = 0; j < 8; ++j) {
                int h = hb + j;
                sS[t * SX + h] = (v[j] - mean) * inv * ln_w[h] + ln_b[h];
            }
        }
    }

    float acc[4][8];

    // ---------------- stage 1: text_emb = l2norm(text_table[ids] @ fc_text_w^T + b) -> sX
    {
#pragma unroll
        for (int p = 0; p < 4; ++p)
#pragma unroll
            for (int j = 0; j < 8; ++j) acc[p][j] = 0.f;
        for (int kc = 0; kc < DTd; kc += KC) {
            __syncthreads();
#pragma unroll
            for (int j = 0; j < 4; ++j) {      // gather A chunk [64][64]
                int idx = tid + j * NTHREADS;  // 0..1023 float4 slots
                int t = idx >> 4, kq = idx & 15;
                float4 v = *reinterpret_cast<const float4*>(
                    text_table + (long)sids[t] * DTd + kc + kq * 4);
                *reinterpret_cast<float4*>(sA + t * SA + kq * 4) = v;
            }
            load_w_chunk(fc_text_w, DTd, kc, sW, tid);
            __syncthreads();
            gemm_chunk4(sA + (ty) * SA, sA + (ty + 16) * SA,
                        sA + (ty + 32) * SA, sA + (ty + 48) * SA, sW, hb, acc);
        }
#pragma unroll
        for (int p = 0; p < 4; ++p) {
            int t = ty + 16 * p;
            float ss = 0.f;
#pragma unroll
            for (int j = 0; j < 8; ++j) {
                acc[p][j] += fc_text_b[hb + j];
                ss += acc[p][j] * acc[p][j];
            }
            ss = hreduce16(ss);
            float sc = 1.f / fmaxf(sqrtf(ss), 1e-12f);
#pragma unroll
            for (int j = 0; j < 8; ++j) sX[t * SX + hb + j] = acc[p][j] * sc;
        }
    }

    // ---------------- stage 2: img_emb -> sY ----------------
    {
#pragma unroll
        for (int p = 0; p < 4; ++p)
#pragma unroll
            for (int j = 0; j < 8; ++j) acc[p][j] = 0.f;
        for (int kc = 0; kc < DId; kc += KC) {
            __syncthreads();
#pragma unroll
            for (int j = 0; j < 4; ++j) {
                int idx = tid + j * NTHREADS;
                int t = idx >> 4, kq = idx & 15;
                float4 v = *reinterpret_cast<const float4*>(
                    img_table + (long)sids[t] * DId + kc + kq * 4);
                *reinterpret_cast<float4*>(sA + t * SA + kq * 4) = v;
            }
            load_w_chunk(fc_img_w, DId, kc, sW, tid);
            __syncthreads();
            gemm_chunk4(sA + (ty) * SA, sA + (ty + 16) * SA,
                        sA + (ty + 32) * SA, sA + (ty + 48) * SA, sW, hb, acc);
        }
#pragma unroll
        for (int p = 0; p < 4; ++p) {
            int t = ty + 16 * p;
            float ss = 0.f;
#pragma unroll
            for (int j = 0; j < 8; ++j) {
                acc[p][j] += fc_img_b[hb + j];
                ss += acc[p][j] * acc[p][j];
            }
            ss = hreduce16(ss);
            float sc = 1.f / fmaxf(sqrtf(ss), 1e-12f);
#pragma unroll
            for (int j = 0; j < 8; ++j) sY[t * SX + hb + j] = acc[p][j] * sc;
        }
    }

    // ---------------- stage 3: VAE reparam text: t_z = mu + exp(sg)*noise -> sX ----------------
    {
        float mu[4][8];
#pragma unroll
        for (int p = 0; p < 4; ++p)
#pragma unroll
            for (int j = 0; j < 8; ++j) acc[p][j] = 0.f;
        for (int kc = 0; kc < Hd; kc += KC) {
            __syncthreads();
            load_w_chunk(mu_t_w, Hd, kc, sW, tid);
            __syncthreads();
            gemm_chunk4(sX + ty * SX + kc, sX + (ty + 16) * SX + kc,
                        sX + (ty + 32) * SX + kc, sX + (ty + 48) * SX + kc, sW, hb, acc);
        }
#pragma unroll
        for (int p = 0; p < 4; ++p)
#pragma unroll
            for (int j = 0; j < 8; ++j) { mu[p][j] = acc[p][j]; acc[p][j] = 0.f; }
        for (int kc = 0; kc < Hd; kc += KC) {
            __syncthreads();
            load_w_chunk(sg_t_w, Hd, kc, sW, tid);
            __syncthreads();
            gemm_chunk4(sX + ty * SX + kc, sX + (ty + 16) * SX + kc,
                        sX + (ty + 32) * SX + kc, sX + (ty + 48) * SX + kc, sW, hb, acc);
        }
        __syncthreads();   // everyone done reading sX
#pragma unroll
        for (int p = 0; p < 4; ++p) {
            int t = ty + 16 * p;
#pragma unroll
            for (int j = 0; j < 8; ++j) {
                int h = hb + j;
                float z = mu[p][j] + mu_t_b[h] +
                          __expf(acc[p][j] + sg_t_b[h]) * t_noise[(long)(n0 + t) * Hd + h];
                sX[t * SX + h] = z;
            }
        }
    }

    // ---------------- stage 4: VAE reparam img -> sY ----------------
    {
        float mu[4][8];
#pragma unroll
        for (int p = 0; p < 4; ++p)
#pragma unroll
            for (int j = 0; j < 8; ++j) acc[p][j] = 0.f;
        for (int kc = 0; kc < Hd; kc += KC) {
            __syncthreads();
            load_w_chunk(mu_i_w, Hd, kc, sW, tid);
            __syncthreads();
            gemm_chunk4(sY + ty * SX + kc, sY + (ty + 16) * SX + kc,
                        sY + (ty + 32) * SX + kc, sY + (ty + 48) * SX + kc, sW, hb, acc);
        }
#pragma unroll
        for (int p = 0; p < 4; ++p)
#pragma unroll
            for (int j = 0; j < 8; ++j) { mu[p][j] = acc[p][j]; acc[p][j] = 0.f; }
        for (int kc = 0; kc < Hd; kc += KC) {
            __syncthreads();
            load_w_chunk(sg_i_w, Hd, kc, sW, tid);
            __syncthreads();
            gemm_chunk4(sY + ty * SX + kc, sY + (ty + 16) * SX + kc,
                        sY + (ty + 32) * SX + kc, sY + (ty + 48) * SX + kc, sW, hb, acc);
        }
        __syncthreads();
#pragma unroll
        for (int p = 0; p < 4; ++p) {
            int t = ty + 16 * p;
#pragma unroll
            for (int j = 0; j < 8; ++j) {
                int h = hb + j;
                float z = mu[p][j] + mu_i_b[h] +
                          __expf(acc[p][j] + sg_i_b[h]) * i_noise[(long)(n0 + t) * Hd + h];
                sY[t * SX + h] = z;
            }
        }
    }

    // ---------------- stage 5: gating (both modalities) ----------------
    __syncthreads();
    {
        int t  = tid >> 2;            // 0..63
        int e0 = (tid & 3) * 2;       // each thread: experts e0, e0+1
#pragma unroll
        for (int q = 0; q < 2; ++q) {
            int e = e0 + q;
            const float* gw = gate_w + e * Hd;
            float dt = 0.f, di = 0.f;
            for (int k = 0; k < Hd; ++k) {
                float w = gw[k];
                dt = fmaf(sX[t * SX + k], w, dt);
                di = fmaf(sY[t * SX + k], w, di);
            }
            sgt[t * Ed + e] = dt + gate_b[e];
            sgi[t * Ed + e] = di + gate_b[e];
        }
    }
    __syncthreads();
    if (tid < TB) {
        route8(sgt + tid * Ed);
        route8(sgi + tid * Ed);
    }
    __syncthreads();

    // ---------------- stage 6: text experts (top-2 sparse, gate-weighted) -> sX ----------------
    {
        float outv[4][8];
#pragma unroll
        for (int p = 0; p < 4; ++p)
#pragma unroll
            for (int j = 0; j < 8; ++j) outv[p][j] = 0.f;
        for (int e = 0; e < Ed; ++e) {
            const float* We = texp_w + (long)e * Hd * Hd;
            float g[4];
#pragma unroll
            for (int p = 0; p < 4; ++p) g[p] = sgt[(ty + 16 * p) * Ed + e];
            float eacc[4][8];
#pragma unroll
            for (int p = 0; p < 4; ++p)
#pragma unroll
                for (int j = 0; j < 8; ++j) eacc[p][j] = 0.f;
            for (int kc = 0; kc < Hd; kc += KC) {
                __syncthreads();
                load_w_chunk(We, Hd, kc, sW, tid);
                __syncthreads();
#pragma unroll
                for (int p = 0; p < 4; ++p) {
                    if (g[p] != 0.f)
                        gemm_chunk1(sX + (ty + 16 * p) * SX + kc, sW, hb, eacc[p]);
                }
            }
#pragma unroll
            for (int p = 0; p < 4; ++p) {
                if (g[p] != 0.f) {
#pragma unroll
                    for (int j = 0; j < 8; ++j)
                        outv[p][j] = fmaf(g[p], eacc[p][j] + texp_b[e * Hd + hb + j], outv[p][j]);
                }
            }
        }
        __syncthreads();
#pragma unroll
        for (int p = 0; p < 4; ++p)
#pragma unroll
            for (int j = 0; j < 8; ++j)
                sX[(ty + 16 * p) * SX + hb + j] = outv[p][j];
    }

    // ---------------- stage 7: img experts -> sY ----------------
    {
        float outv[4][8];
#pragma unroll
        for (int p = 0; p < 4; ++p)
#pragma unroll
            for (int j = 0; j < 8; ++j) outv[p][j] = 0.f;
        for (int e = 0; e < Ed; ++e) {
            const float* We = iexp_w + (long)e * Hd * Hd;
            float g[4];
#pragma unroll
            for (int p = 0; p < 4; ++p) g[p] = sgi[(ty + 16 * p) * Ed + e];
            float eacc[4][8];
#pragma unroll
            for (int p = 0; p < 4; ++p)
#pragma unroll
                for (int j = 0; j < 8; ++j) eacc[p][j] = 0.f;
            for (int kc = 0; kc < Hd; kc += KC) {
                __syncthreads();
                load_w_chunk(We, Hd, kc, sW, tid);
                __syncthreads();
#pragma unroll
                for (int p = 0; p < 4; ++p) {
                    if (g[p] != 0.f)
                        gemm_chunk1(sY + (ty + 16 * p) * SX + kc, sW, hb, eacc[p]);
                }
            }
#pragma unroll
            for (int p = 0; p < 4; ++p) {
                if (g[p] != 0.f) {
#pragma unroll
                    for (int j = 0; j < 8; ++j)
                        outv[p][j] = fmaf(g[p], eacc[p][j] + iexp_b[e * Hd + hb + j], outv[p][j]);
                }
            }
        }
        __syncthreads();
#pragma unroll
        for (int p = 0; p < 4; ++p)
#pragma unroll
            for (int j = 0; j < 8; ++j)
                sY[(ty + 16 * p) * SX + hb + j] = outv[p][j];
    }
    __syncthreads();

    // ---------------- stage 8: fusion = seq + relu(LN(cat(t,i) @ fus_w^T + b)) ----------------
    {
#pragma unroll
        for (int p = 0; p < 4; ++p)
#pragma unroll
            for (int j = 0; j < 8; ++j) acc[p][j] = 0.f;
        for (int kc = 0; kc < 2 * Hd; kc += KC) {
            __syncthreads();
            load_w_chunk(fus_w, 2 * Hd, kc, sW, tid);
            __syncthreads();
            const float* base = (kc < Hd) ? sX : sY;
            int ko = (kc < Hd) ? kc : (kc - Hd);
            gemm_chunk4(base + ty * SX + ko, base + (ty + 16) * SX + ko,
                        base + (ty + 32) * SX + ko, base + (ty + 48) * SX + ko,
                        sW, hb, acc);
        }
#pragma unroll
        for (int p = 0; p < 4; ++p) {
            int t = ty + 16 * p;
            float s = 0.f, sq = 0.f;
#pragma unroll
            for (int j = 0; j < 8; ++j) {
                acc[p][j] += fus_b[hb + j];
                s += acc[p][j]; sq += acc[p][j] * acc[p][j];
            }
            s  = hreduce16(s);
            sq = hreduce16(sq);
            float mean = s * (1.f / Hd);
            float var  = sq * (1.f / Hd) - mean * mean;
            float inv  = rsqrtf(var + 1e-5f);
            long n = n0 + t;
#pragma unroll
            for (int j = 0; j < 8; ++j) {
                int h = hb + j;
                float y = (acc[p][j] - mean) * inv * fus_ln_w[h] + fus_ln_b[h];
                out[n * Hd + h] = fmaxf(y, 0.f) + sS[t * SX + h];
            }
        }
    }
}

extern "C" void kernel_launch(void* const* d_in, const int* in_sizes, int n_in,
                              void* d_out, int out_size) {
    (void)in_sizes; (void)n_in; (void)out_size;
    const int*   input_ids  = (const int*)  d_in[0];
    const float* t_noise    = (const float*)d_in[1];
    const float* i_noise    = (const float*)d_in[2];
    const float* item_table = (const float*)d_in[3];
    const float* pos_table  = (const float*)d_in[4];
    const float* text_table = (const float*)d_in[5];
    const float* img_table  = (const float*)d_in[6];
    const float* fc_text_w  = (const float*)d_in[7];
    const float* fc_text_b  = (const float*)d_in[8];
    const float* fc_img_w   = (const float*)d_in[9];
    const float* fc_img_b   = (const float*)d_in[10];
    const float* ln_w       = (const float*)d_in[11];
    const float* ln_b       = (const float*)d_in[12];
    const float* mu_t_w     = (const float*)d_in[13];
    const float* mu_t_b     = (const float*)d_in[14];
    const float* sg_t_w     = (const float*)d_in[15];
    const float* sg_t_b     = (const float*)d_in[16];
    const float* mu_i_w     = (const float*)d_in[17];
    const float* mu_i_b     = (const float*)d_in[18];
    const float* sg_i_w     = (const float*)d_in[19];
    const float* sg_i_b     = (const float*)d_in[20];
    const float* gate_w     = (const float*)d_in[21];
    const float* gate_b     = (const float*)d_in[22];
    const float* texp_w     = (const float*)d_in[23];
    const float* texp_b     = (const float*)d_in[24];
    const float* iexp_w     = (const float*)d_in[25];
    const float* iexp_b     = (const float*)d_in[26];
    const float* fus_w      = (const float*)d_in[27];
    const float* fus_b      = (const float*)d_in[28];
    const float* fus_ln_w   = (const float*)d_in[29];
    const float* fus_ln_b   = (const float*)d_in[30];

    size_t smem = SMEM_FLOATS * sizeof(float);
    cudaFuncSetAttribute(sasrec_fused_kernel,
                         cudaFuncAttributeMaxDynamicSharedMemorySize, (int)smem);

    sasrec_fused_kernel<<<NTOK / TB, NTHREADS, smem>>>(
        input_ids, t_noise, i_noise, item_table, pos_table, text_table, img_table,
        fc_text_w, fc_text_b, fc_img_w, fc_img_b, ln_w, ln_b,
        mu_t_w, mu_t_b, sg_t_w, sg_t_b, mu_i_w, mu_i_b, sg_i_w, sg_i_b,
        gate_w, gate_b, texp_w, texp_b, iexp_w, iexp_b,
        fus_w, fus_b, fus_ln_w, fus_ln_b,
        (float*)d_out);
}

// round 3
// speedup vs baseline: 1.7774x; 1.0955x over previous
#include <cuda_runtime.h>
#include <math.h>

#define Hd      128
#define Ld      200
#define DTd     768
#define DId     512
#define Ed      8
#define NTOK    25600
#define TB      64
#define NTHREADS 256
#define KC      32
#define SW      132   // s_W row stride (k-major: s_W[k*SW + h])
#define SA      36    // gathered-A chunk row stride
#define SX      132   // persistent activation row stride

// shared memory layout (float offsets)
#define OFF_W   0                      // 32*132 = 4224
#define OFF_A   4224                   // 64*36  = 2304
#define OFF_X   6528                   // 64*132 = 8448
#define OFF_Y   14976                  // 8448
#define OFF_GT  23424                  // 64*8 = 512
#define OFF_GI  23936                  // 512
#define OFF_IDS 24448                  // 64
#define SMEM_FLOATS 24512              // 98048 bytes -> 2 CTAs/SM

__device__ __forceinline__ float hreduce16(float v) {
    v += __shfl_xor_sync(0xffffffffu, v, 1);
    v += __shfl_xor_sync(0xffffffffu, v, 2);
    v += __shfl_xor_sync(0xffffffffu, v, 4);
    v += __shfl_xor_sync(0xffffffffu, v, 8);
    return v;
}

// Load a [128 x KC=32] weight chunk (row-major, leading dim ldw) into smem transposed:
// s_W[k*SW + h].
__device__ __forceinline__ void load_w_chunk(const float* __restrict__ Wg, int ldw, int kc,
                                             float* __restrict__ sW, int tid) {
#pragma unroll
    for (int j = 0; j < 4; ++j) {
        int idx = tid + j * NTHREADS;          // 0..1023 float4 slots
        int h   = idx >> 3;                    // 8 float4 per output row (32 floats)
        int k4  = (idx & 7) * 4;
        float4 v = *reinterpret_cast<const float4*>(Wg + (long)h * ldw + kc + k4);
        sW[(k4 + 0) * SW + h] = v.x;
        sW[(k4 + 1) * SW + h] = v.y;
        sW[(k4 + 2) * SW + h] = v.z;
        sW[(k4 + 3) * SW + h] = v.w;
    }
}

// Gather [64 x 32] activation chunk from an embedding table into sA.
__device__ __forceinline__ void gather_a_chunk(const float* __restrict__ table, int ldw, int kc,
                                               const int* __restrict__ sids,
                                               float* __restrict__ sA, int tid) {
#pragma unroll
    for (int j = 0; j < 2; ++j) {
        int idx = tid + j * NTHREADS;          // 0..511 float4 slots
        int t  = idx >> 3;
        int kq = (idx & 7) * 4;
        float4 v = *reinterpret_cast<const float4*>(table + (long)sids[t] * ldw + kc + kq);
        *reinterpret_cast<float4*>(sA + t * SA + kq) = v;
    }
}

// 4 tokens x 8 outputs, KC=32.
__device__ __forceinline__ void gemm_chunk4(const float* __restrict__ a0,
                                            const float* __restrict__ a1,
                                            const float* __restrict__ a2,
                                            const float* __restrict__ a3,
                                            const float* __restrict__ sW,
                                            int hb, float acc[4][8]) {
#pragma unroll 8
    for (int k = 0; k < KC; ++k) {
        const float* wp = sW + k * SW + hb;
        float4 b0 = *reinterpret_cast<const float4*>(wp);
        float4 b1 = *reinterpret_cast<const float4*>(wp + 4);
        float b[8] = {b0.x, b0.y, b0.z, b0.w, b1.x, b1.y, b1.z, b1.w};
        float av[4] = {a0[k], a1[k], a2[k], a3[k]};
#pragma unroll
        for (int p = 0; p < 4; ++p)
#pragma unroll
            for (int j = 0; j < 8; ++j)
                acc[p][j] = fmaf(av[p], b[j], acc[p][j]);
    }
}

// 2 tokens x 8 outputs, KC=32 (VAE half-passes).
__device__ __forceinline__ void gemm_chunk2(const float* __restrict__ a0,
                                            const float* __restrict__ a1,
                                            const float* __restrict__ sW,
                                            int hb, float acc[2][8]) {
#pragma unroll 8
    for (int k = 0; k < KC; ++k) {
        const float* wp = sW + k * SW + hb;
        float4 b0 = *reinterpret_cast<const float4*>(wp);
        float4 b1 = *reinterpret_cast<const float4*>(wp + 4);
        float b[8] = {b0.x, b0.y, b0.z, b0.w, b1.x, b1.y, b1.z, b1.w};
        float av0 = a0[k], av1 = a1[k];
#pragma unroll
        for (int j = 0; j < 8; ++j) {
            acc[0][j] = fmaf(av0, b[j], acc[0][j]);
            acc[1][j] = fmaf(av1, b[j], acc[1][j]);
        }
    }
}

// 1 token x 8 outputs, gate folded into A (expert stage).
__device__ __forceinline__ void gemm_gated(const float* __restrict__ a, float g,
                                           const float* __restrict__ sW,
                                           int hb, float acc[8]) {
#pragma unroll 8
    for (int k = 0; k < KC; ++k) {
        const float* wp = sW + k * SW + hb;
        float4 b0 = *reinterpret_cast<const float4*>(wp);
        float4 b1 = *reinterpret_cast<const float4*>(wp + 4);
        float av = a[k] * g;
        acc[0] = fmaf(av, b0.x, acc[0]);
        acc[1] = fmaf(av, b0.y, acc[1]);
        acc[2] = fmaf(av, b0.z, acc[2]);
        acc[3] = fmaf(av, b0.w, acc[3]);
        acc[4] = fmaf(av, b1.x, acc[4]);
        acc[5] = fmaf(av, b1.y, acc[5]);
        acc[6] = fmaf(av, b1.z, acc[6]);
        acc[7] = fmaf(av, b1.w, acc[7]);
    }
}

// softmax over 8 -> keep top-2 (earliest index on ties) -> renorm
__device__ __forceinline__ void route8(float* g) {
    float m = g[0];
#pragma unroll
    for (int e = 1; e < Ed; ++e) m = fmaxf(m, g[e]);
    float ex[Ed]; float s = 0.f;
#pragma unroll
    for (int e = 0; e < Ed; ++e) { ex[e] = __expf(g[e] - m); s += ex[e]; }
    float inv = 1.f / s;
#pragma unroll
    for (int e = 0; e < Ed; ++e) ex[e] *= inv;
    int i1 = 0; float w1 = ex[0];
#pragma unroll
    for (int e = 1; e < Ed; ++e) if (ex[e] > w1) { w1 = ex[e]; i1 = e; }
    int i2 = -1; float w2 = -1.f;
#pragma unroll
    for (int e = 0; e < Ed; ++e) if (e != i1 && ex[e] > w2) { w2 = ex[e]; i2 = e; }
    float den = 1.f / (w1 + w2 + 1e-8f);
#pragma unroll
    for (int e = 0; e < Ed; ++e)
        g[e] = (e == i1) ? w1 * den : ((e == i2) ? w2 * den : 0.f);
}

__global__ __launch_bounds__(NTHREADS, 2)
void sasrec_fused_kernel(
    const int*   __restrict__ input_ids,
    const float* __restrict__ t_noise,   const float* __restrict__ i_noise,
    const float* __restrict__ item_table,const float* __restrict__ pos_table,
    const float* __restrict__ text_table,const float* __restrict__ img_table,
    const float* __restrict__ fc_text_w, const float* __restrict__ fc_text_b,
    const float* __restrict__ fc_img_w,  const float* __restrict__ fc_img_b,
    const float* __restrict__ ln_w,      const float* __restrict__ ln_b,
    const float* __restrict__ mu_t_w,    const float* __restrict__ mu_t_b,
    const float* __restrict__ sg_t_w,    const float* __restrict__ sg_t_b,
    const float* __restrict__ mu_i_w,    const float* __restrict__ mu_i_b,
    const float* __restrict__ sg_i_w,    const float* __restrict__ sg_i_b,
    const float* __restrict__ gate_w,    const float* __restrict__ gate_b,
    const float* __restrict__ texp_w,    const float* __restrict__ texp_b,
    const float* __restrict__ iexp_w,    const float* __restrict__ iexp_b,
    const float* __restrict__ fus_w,     const float* __restrict__ fus_b,
    const float* __restrict__ fus_ln_w,  const float* __restrict__ fus_ln_b,
    float*       __restrict__ out)
{
    extern __shared__ float sm[];
    float* sW  = sm + OFF_W;
    float* sA  = sm + OFF_A;
    float* sX  = sm + OFF_X;
    float* sY  = sm + OFF_Y;
    float* sgt = sm + OFF_GT;
    float* sgi = sm + OFF_GI;
    int*   sids = (int*)(sm + OFF_IDS);

    const int tid = threadIdx.x;
    const int tx  = tid & 15;
    const int ty  = tid >> 4;          // 0..15
    const int hb  = tx * 8;
    const int n0  = blockIdx.x * TB;

    if (tid < TB) sids[tid] = input_ids[n0 + tid];
    __syncthreads();

    float acc[4][8];

    // ---------------- stage 1: text_emb = l2norm(text_table[ids] @ fc_text_w^T + b) -> sX
    {
#pragma unroll
        for (int p = 0; p < 4; ++p)
#pragma unroll
            for (int j = 0; j < 8; ++j) acc[p][j] = 0.f;
        for (int kc = 0; kc < DTd; kc += KC) {
            __syncthreads();
            gather_a_chunk(text_table, DTd, kc, sids, sA, tid);
            load_w_chunk(fc_text_w, DTd, kc, sW, tid);
            __syncthreads();
            gemm_chunk4(sA + ty * SA, sA + (ty + 16) * SA,
                        sA + (ty + 32) * SA, sA + (ty + 48) * SA, sW, hb, acc);
        }
#pragma unroll
        for (int p = 0; p < 4; ++p) {
            int t = ty + 16 * p;
            float ss = 0.f;
#pragma unroll
            for (int j = 0; j < 8; ++j) {
                acc[p][j] += fc_text_b[hb + j];
                ss += acc[p][j] * acc[p][j];
            }
            ss = hreduce16(ss);
            float sc = 1.f / fmaxf(sqrtf(ss), 1e-12f);
#pragma unroll
            for (int j = 0; j < 8; ++j) sX[t * SX + hb + j] = acc[p][j] * sc;
        }
    }

    // ---------------- stage 2: img_emb -> sY ----------------
    {
#pragma unroll
        for (int p = 0; p < 4; ++p)
#pragma unroll
            for (int j = 0; j < 8; ++j) acc[p][j] = 0.f;
        for (int kc = 0; kc < DId; kc += KC) {
            __syncthreads();
            gather_a_chunk(img_table, DId, kc, sids, sA, tid);
            load_w_chunk(fc_img_w, DId, kc, sW, tid);
            __syncthreads();
            gemm_chunk4(sA + ty * SA, sA + (ty + 16) * SA,
                        sA + (ty + 32) * SA, sA + (ty + 48) * SA, sW, hb, acc);
        }
#pragma unroll
        for (int p = 0; p < 4; ++p) {
            int t = ty + 16 * p;
            float ss = 0.f;
#pragma unroll
            for (int j = 0; j < 8; ++j) {
                acc[p][j] += fc_img_b[hb + j];
                ss += acc[p][j] * acc[p][j];
            }
            ss = hreduce16(ss);
            float sc = 1.f / fmaxf(sqrtf(ss), 1e-12f);
#pragma unroll
            for (int j = 0; j < 8; ++j) sY[t * SX + hb + j] = acc[p][j] * sc;
        }
    }

    // ---------------- stage 3: VAE reparam text (two half-token passes) -> sX ----------------
#pragma unroll 1
    for (int q = 0; q < 2; ++q) {
        const int tA = ty + 32 * q;            // tokens tA, tA+16
        float mu2[2][8], sg2[2][8];
#pragma unroll
        for (int p = 0; p < 2; ++p)
#pragma unroll
            for (int j = 0; j < 8; ++j) { mu2[p][j] = 0.f; sg2[p][j] = 0.f; }
        for (int kc = 0; kc < Hd; kc += KC) {
            __syncthreads();
            load_w_chunk(mu_t_w, Hd, kc, sW, tid);
            __syncthreads();
            gemm_chunk2(sX + tA * SX + kc, sX + (tA + 16) * SX + kc, sW, hb, mu2);
        }
        for (int kc = 0; kc < Hd; kc += KC) {
            __syncthreads();
            load_w_chunk(sg_t_w, Hd, kc, sW, tid);
            __syncthreads();
            gemm_chunk2(sX + tA * SX + kc, sX + (tA + 16) * SX + kc, sW, hb, sg2);
        }
#pragma unroll
        for (int p = 0; p < 2; ++p) {
            int t = tA + 16 * p;
#pragma unroll
            for (int j = 0; j < 8; ++j) {
                int h = hb + j;
                float z = mu2[p][j] + mu_t_b[h] +
                          __expf(sg2[p][j] + sg_t_b[h]) * t_noise[(long)(n0 + t) * Hd + h];
                sX[t * SX + h] = z;
            }
        }
    }

    // ---------------- stage 4: VAE reparam img (two half-token passes) -> sY ----------------
#pragma unroll 1
    for (int q = 0; q < 2; ++q) {
        const int tA = ty + 32 * q;
        float mu2[2][8], sg2[2][8];
#pragma unroll
        for (int p = 0; p < 2; ++p)
#pragma unroll
            for (int j = 0; j < 8; ++j) { mu2[p][j] = 0.f; sg2[p][j] = 0.f; }
        for (int kc = 0; kc < Hd; kc += KC) {
            __syncthreads();
            load_w_chunk(mu_i_w, Hd, kc, sW, tid);
            __syncthreads();
            gemm_chunk2(sY + tA * SX + kc, sY + (tA + 16) * SX + kc, sW, hb, mu2);
        }
        for (int kc = 0; kc < Hd; kc += KC) {
            __syncthreads();
            load_w_chunk(sg_i_w, Hd, kc, sW, tid);
            __syncthreads();
            gemm_chunk2(sY + tA * SX + kc, sY + (tA + 16) * SX + kc, sW, hb, sg2);
        }
#pragma unroll
        for (int p = 0; p < 2; ++p) {
            int t = tA + 16 * p;
#pragma unroll
            for (int j = 0; j < 8; ++j) {
                int h = hb + j;
                float z = mu2[p][j] + mu_i_b[h] +
                          __expf(sg2[p][j] + sg_i_b[h]) * i_noise[(long)(n0 + t) * Hd + h];
                sY[t * SX + h] = z;
            }
        }
    }

    // ---------------- stage 5: gating (both modalities) ----------------
    __syncthreads();
    {
        int t  = tid >> 2;            // 0..63
        int e0 = (tid & 3) * 2;       // each thread: experts e0, e0+1
#pragma unroll
        for (int qe = 0; qe < 2; ++qe) {
            int e = e0 + qe;
            const float* gw = gate_w + e * Hd;
            float dt = 0.f, di = 0.f;
            for (int k = 0; k < Hd; ++k) {
                float w = gw[k];
                dt = fmaf(sX[t * SX + k], w, dt);
                di = fmaf(sY[t * SX + k], w, di);
            }
            sgt[t * Ed + e] = dt + gate_b[e];
            sgi[t * Ed + e] = di + gate_b[e];
        }
    }
    __syncthreads();
    if (tid < TB) {
        route8(sgt + tid * Ed);
        route8(sgi + tid * Ed);
    }
    __syncthreads();

    // ---------------- stage 6: text experts (top-2 sparse, gate folded into A) -> sX ----------------
    {
        float outv[4][8];
        // init with gate-weighted biases
#pragma unroll
        for (int p = 0; p < 4; ++p) {
            int t = ty + 16 * p;
#pragma unroll
            for (int j = 0; j < 8; ++j) outv[p][j] = 0.f;
#pragma unroll
            for (int e = 0; e < Ed; ++e) {
                float g = sgt[t * Ed + e];
                if (g != 0.f) {
#pragma unroll
                    for (int j = 0; j < 8; ++j)
                        outv[p][j] = fmaf(g, texp_b[e * Hd + hb + j], outv[p][j]);
                }
            }
        }
#pragma unroll 1
        for (int e = 0; e < Ed; ++e) {
            const float* We = texp_w + (long)e * Hd * Hd;
#pragma unroll 1
            for (int kc = 0; kc < Hd; kc += KC) {
                __syncthreads();
                load_w_chunk(We, Hd, kc, sW, tid);
                __syncthreads();
#pragma unroll
                for (int p = 0; p < 4; ++p) {
                    float g = sgt[(ty + 16 * p) * Ed + e];
                    if (g != 0.f)
                        gemm_gated(sX + (ty + 16 * p) * SX + kc, g, sW, hb, outv[p]);
                }
            }
        }
        __syncthreads();
#pragma unroll
        for (int p = 0; p < 4; ++p)
#pragma unroll
            for (int j = 0; j < 8; ++j)
                sX[(ty + 16 * p) * SX + hb + j] = outv[p][j];
    }

    // ---------------- stage 7: img experts -> sY ----------------
    {
        float outv[4][8];
#pragma unroll
        for (int p = 0; p < 4; ++p) {
            int t = ty + 16 * p;
#pragma unroll
            for (int j = 0; j < 8; ++j) outv[p][j] = 0.f;
#pragma unroll
            for (int e = 0; e < Ed; ++e) {
                float g = sgi[t * Ed + e];
                if (g != 0.f) {
#pragma unroll
                    for (int j = 0; j < 8; ++j)
                        outv[p][j] = fmaf(g, iexp_b[e * Hd + hb + j], outv[p][j]);
                }
            }
        }
#pragma unroll 1
        for (int e = 0; e < Ed; ++e) {
            const float* We = iexp_w + (long)e * Hd * Hd;
#pragma unroll 1
            for (int kc = 0; kc < Hd; kc += KC) {
                __syncthreads();
                load_w_chunk(We, Hd, kc, sW, tid);
                __syncthreads();
#pragma unroll
                for (int p = 0; p < 4; ++p) {
                    float g = sgi[(ty + 16 * p) * Ed + e];
                    if (g != 0.f)
                        gemm_gated(sY + (ty + 16 * p) * SX + kc, g, sW, hb, outv[p]);
                }
            }
        }
        __syncthreads();
#pragma unroll
        for (int p = 0; p < 4; ++p)
#pragma unroll
            for (int j = 0; j < 8; ++j)
                sY[(ty + 16 * p) * SX + hb + j] = outv[p][j];
    }

    // ---------------- stage 8: fusion + recomputed seq_emb ----------------
    {
#pragma unroll
        for (int p = 0; p < 4; ++p)
#pragma unroll
            for (int j = 0; j < 8; ++j) acc[p][j] = 0.f;
        for (int kc = 0; kc < 2 * Hd; kc += KC) {
            __syncthreads();
            load_w_chunk(fus_w, 2 * Hd, kc, sW, tid);
            __syncthreads();
            const float* base = (kc < Hd) ? sX : sY;
            int ko = (kc < Hd) ? kc : (kc - Hd);
            gemm_chunk4(base + ty * SX + ko, base + (ty + 16) * SX + ko,
                        base + (ty + 32) * SX + ko, base + (ty + 48) * SX + ko,
                        sW, hb, acc);
        }
#pragma unroll
        for (int p = 0; p < 4; ++p) {
            int t = ty + 16 * p;
            int n = n0 + t;
            // fusion LN
            float s = 0.f, sq = 0.f;
#pragma unroll
            for (int j = 0; j < 8; ++j) {
                acc[p][j] += fus_b[hb + j];
                s += acc[p][j]; sq += acc[p][j] * acc[p][j];
            }
            s  = hreduce16(s);
            sq = hreduce16(sq);
            float mean = s * (1.f / Hd);
            float var  = sq * (1.f / Hd) - mean * mean;
            float inv  = rsqrtf(var + 1e-5f);
            // recompute seq_emb = LN(item + pos)
            int id  = sids[t];
            int pos = n % Ld;
            float v[8]; float s2 = 0.f, sq2 = 0.f;
#pragma unroll
            for (int j = 0; j < 8; ++j) {
                int h = hb + j;
                float x = item_table[(long)id * Hd + h] + pos_table[pos * Hd + h];
                v[j] = x; s2 += x; sq2 += x * x;
            }
            s2  = hreduce16(s2);
            sq2 = hreduce16(sq2);
            float mean2 = s2 * (1.f / Hd);
            float var2  = sq2 * (1.f / Hd) - mean2 * mean2;
            float inv2  = rsqrtf(var2 + 1e-12f);
#pragma unroll
            for (int j = 0; j < 8; ++j) {
                int h = hb + j;
                float y   = (acc[p][j] - mean) * inv * fus_ln_w[h] + fus_ln_b[h];
                float seq = (v[j] - mean2) * inv2 * ln_w[h] + ln_b[h];
                out[(long)n * Hd + h] = fmaxf(y, 0.f) + seq;
            }
        }
    }
}

extern "C" void kernel_launch(void* const* d_in, const int* in_sizes, int n_in,
                              void* d_out, int out_size) {
    (void)in_sizes; (void)n_in; (void)out_size;
    const int*   input_ids  = (const int*)  d_in[0];
    const float* t_noise    = (const float*)d_in[1];
    const float* i_noise    = (const float*)d_in[2];
    const float* item_table = (const float*)d_in[3];
    const float* pos_table  = (const float*)d_in[4];
    const float* text_table = (const float*)d_in[5];
    const float* img_table  = (const float*)d_in[6];
    const float* fc_text_w  = (const float*)d_in[7];
    const float* fc_text_b  = (const float*)d_in[8];
    const float* fc_img_w   = (const float*)d_in[9];
    const float* fc_img_b   = (const float*)d_in[10];
    const float* ln_w       = (const float*)d_in[11];
    const float* ln_b       = (const float*)d_in[12];
    const float* mu_t_w     = (const float*)d_in[13];
    const float* mu_t_b     = (const float*)d_in[14];
    const float* sg_t_w     = (const float*)d_in[15];
    const float* sg_t_b     = (const float*)d_in[16];
    const float* mu_i_w     = (const float*)d_in[17];
    const float* mu_i_b     = (const float*)d_in[18];
    const float* sg_i_w     = (const float*)d_in[19];
    const float* sg_i_b     = (const float*)d_in[20];
    const float* gate_w     = (const float*)d_in[21];
    const float* gate_b     = (const float*)d_in[22];
    const float* texp_w     = (const float*)d_in[23];
    const float* texp_b     = (const float*)d_in[24];
    const float* iexp_w     = (const float*)d_in[25];
    const float* iexp_b     = (const float*)d_in[26];
    const float* fus_w      = (const float*)d_in[27];
    const float* fus_b      = (const float*)d_in[28];
    const float* fus_ln_w   = (const float*)d_in[29];
    const float* fus_ln_b   = (const float*)d_in[30];

    size_t smem = SMEM_FLOATS * sizeof(float);
    cudaFuncSetAttribute(sasrec_fused_kernel,
                         cudaFuncAttributeMaxDynamicSharedMemorySize, (int)smem);

    sasrec_fused_kernel<<<NTOK / TB, NTHREADS, smem>>>(
        input_ids, t_noise, i_noise, item_table, pos_table, text_table, img_table,
        fc_text_w, fc_text_b, fc_img_w, fc_img_b, ln_w, ln_b,
        mu_t_w, mu_t_b, sg_t_w, sg_t_b, mu_i_w, mu_i_b, sg_i_w, sg_i_b,
        gate_w, gate_b, texp_w, texp_b, iexp_w, iexp_b,
        fus_w, fus_b, fus_ln_w, fus_ln_b,
        (float*)d_out);
}

// round 4
// speedup vs baseline: 2.4096x; 1.3556x over previous
#include <cuda_runtime.h>
#include <math.h>

#define Hd      128
#define Ld      200
#define DTd     768
#define DId     512
#define Ed      8
#define NTOK    25600
#define TB      64
#define NTHREADS 256
#define KC      32
#define SWROW   128   // floats per swizzled weight k-row
#define SA      36    // gathered-A chunk row stride
#define SX      132   // persistent activation row stride

// shared memory layout (float offsets)
#define OFF_W   0                      // 32*128 = 4096
#define OFF_A   4096                   // 64*36  = 2304
#define OFF_X   6400                   // 64*132 = 8448
#define OFF_Y   14848                  // 8448
#define OFF_GT  23296                  // 512
#define OFF_GI  23808                  // 512
#define OFF_IDS 24320                  // 64
#define SMEM_FLOATS 24384              // 97536 bytes -> 2 CTAs/SM

__device__ __forceinline__ float hreduce16(float v) {
    v += __shfl_xor_sync(0xffffffffu, v, 1);
    v += __shfl_xor_sync(0xffffffffu, v, 2);
    v += __shfl_xor_sync(0xffffffffu, v, 4);
    v += __shfl_xor_sync(0xffffffffu, v, 8);
    return v;
}

// Load a [128 x KC=32] weight chunk into smem, transposed + XOR-swizzled:
// element (k, h) lives at sW[k*128 + ((h>>2) ^ ((k>>2)&7))*4 + (h&3)].
// Stores hit all 32 banks (conflict-free); reads are 16B-aligned permutations.
__device__ __forceinline__ void load_w_chunk(const float* __restrict__ Wg, int ldw, int kc,
                                             float* __restrict__ sW, int tid) {
#pragma unroll
    for (int j = 0; j < 4; ++j) {
        int idx = tid + j * NTHREADS;          // 0..1023 float4 slots
        int h   = idx >> 3;                    // 0..127
        int k4  = (idx & 7) * 4;               // 0..28
        float4 v = *reinterpret_cast<const float4*>(Wg + (long)h * ldw + kc + k4);
        int m  = (k4 >> 2) & 7;
        int fb = (((h >> 2) ^ m) << 2) + (h & 3);
        float* dst = sW + k4 * SWROW + fb;
        dst[0 * SWROW] = v.x;
        dst[1 * SWROW] = v.y;
        dst[2 * SWROW] = v.z;
        dst[3 * SWROW] = v.w;
    }
}

// Gather [64 x 32] activation chunk from an embedding table into sA.
__device__ __forceinline__ void gather_a_chunk(const float* __restrict__ table, int ldw, int kc,
                                               const int* __restrict__ sids,
                                               float* __restrict__ sA, int tid) {
#pragma unroll
    for (int j = 0; j < 2; ++j) {
        int idx = tid + j * NTHREADS;          // 0..511 float4 slots
        int t  = idx >> 3;
        int kq = (idx & 7) * 4;
        float4 v = *reinterpret_cast<const float4*>(table + (long)sids[t] * ldw + kc + kq);
        *reinterpret_cast<float4*>(sA + t * SA + kq) = v;
    }
}

// 4 tokens x 8 outputs (h = tx*4+{0..3} and tx*4+64+{0..3}), KC=32, swizzled W reads.
__device__ __forceinline__ void gemm_chunk4(const float* __restrict__ a0,
                                            const float* __restrict__ a1,
                                            const float* __restrict__ a2,
                                            const float* __restrict__ a3,
                                            const float* __restrict__ sW,
                                            int tx, float acc[4][8]) {
#pragma unroll
    for (int k4 = 0; k4 < KC; k4 += 4) {
        const int m = (k4 >> 2) & 7;
        const float* wlo = sW + k4 * SWROW + ((tx ^ m) << 2);
        float4 A0 = *reinterpret_cast<const float4*>(a0 + k4);
        float4 A1 = *reinterpret_cast<const float4*>(a1 + k4);
        float4 A2 = *reinterpret_cast<const float4*>(a2 + k4);
        float4 A3 = *reinterpret_cast<const float4*>(a3 + k4);
        float av[4][4] = {{A0.x, A0.y, A0.z, A0.w}, {A1.x, A1.y, A1.z, A1.w},
                          {A2.x, A2.y, A2.z, A2.w}, {A3.x, A3.y, A3.z, A3.w}};
#pragma unroll
        for (int kk = 0; kk < 4; ++kk) {
            float4 b0 = *reinterpret_cast<const float4*>(wlo + kk * SWROW);
            float4 b1 = *reinterpret_cast<const float4*>(wlo + kk * SWROW + 64);
            float b[8] = {b0.x, b0.y, b0.z, b0.w, b1.x, b1.y, b1.z, b1.w};
#pragma unroll
            for (int p = 0; p < 4; ++p)
#pragma unroll
                for (int j = 0; j < 8; ++j)
                    acc[p][j] = fmaf(av[p][kk], b[j], acc[p][j]);
        }
    }
}

// 2 tokens x 8 outputs (VAE half-passes).
__device__ __forceinline__ void gemm_chunk2(const float* __restrict__ a0,
                                            const float* __restrict__ a1,
                                            const float* __restrict__ sW,
                                            int tx, float acc[2][8]) {
#pragma unroll
    for (int k4 = 0; k4 < KC; k4 += 4) {
        const int m = (k4 >> 2) & 7;
        const float* wlo = sW + k4 * SWROW + ((tx ^ m) << 2);
        float4 A0 = *reinterpret_cast<const float4*>(a0 + k4);
        float4 A1 = *reinterpret_cast<const float4*>(a1 + k4);
        float av[2][4] = {{A0.x, A0.y, A0.z, A0.w}, {A1.x, A1.y, A1.z, A1.w}};
#pragma unroll
        for (int kk = 0; kk < 4; ++kk) {
            float4 b0 = *reinterpret_cast<const float4*>(wlo + kk * SWROW);
            float4 b1 = *reinterpret_cast<const float4*>(wlo + kk * SWROW + 64);
            float b[8] = {b0.x, b0.y, b0.z, b0.w, b1.x, b1.y, b1.z, b1.w};
#pragma unroll
            for (int j = 0; j < 8; ++j) {
                acc[0][j] = fmaf(av[0][kk], b[j], acc[0][j]);
                acc[1][j] = fmaf(av[1][kk], b[j], acc[1][j]);
            }
        }
    }
}

// 1 token x 8 outputs, gate folded into A (expert stage).
__device__ __forceinline__ void gemm_gated(const float* __restrict__ a, float g,
                                           const float* __restrict__ sW,
                                           int tx, float acc[8]) {
#pragma unroll
    for (int k4 = 0; k4 < KC; k4 += 4) {
        const int m = (k4 >> 2) & 7;
        const float* wlo = sW + k4 * SWROW + ((tx ^ m) << 2);
        float4 A0 = *reinterpret_cast<const float4*>(a + k4);
        float av[4] = {A0.x * g, A0.y * g, A0.z * g, A0.w * g};
#pragma unroll
        for (int kk = 0; kk < 4; ++kk) {
            float4 b0 = *reinterpret_cast<const float4*>(wlo + kk * SWROW);
            float4 b1 = *reinterpret_cast<const float4*>(wlo + kk * SWROW + 64);
            acc[0] = fmaf(av[kk], b0.x, acc[0]);
            acc[1] = fmaf(av[kk], b0.y, acc[1]);
            acc[2] = fmaf(av[kk], b0.z, acc[2]);
            acc[3] = fmaf(av[kk], b0.w, acc[3]);
            acc[4] = fmaf(av[kk], b1.x, acc[4]);
            acc[5] = fmaf(av[kk], b1.y, acc[5]);
            acc[6] = fmaf(av[kk], b1.z, acc[6]);
            acc[7] = fmaf(av[kk], b1.w, acc[7]);
        }
    }
}

// softmax over 8 -> keep top-2 (earliest index on ties) -> renorm
__device__ __forceinline__ void route8(float* g) {
    float m = g[0];
#pragma unroll
    for (int e = 1; e < Ed; ++e) m = fmaxf(m, g[e]);
    float ex[Ed]; float s = 0.f;
#pragma unroll
    for (int e = 0; e < Ed; ++e) { ex[e] = __expf(g[e] - m); s += ex[e]; }
    float inv = 1.f / s;
#pragma unroll
    for (int e = 0; e < Ed; ++e) ex[e] *= inv;
    int i1 = 0; float w1 = ex[0];
#pragma unroll
    for (int e = 1; e < Ed; ++e) if (ex[e] > w1) { w1 = ex[e]; i1 = e; }
    int i2 = -1; float w2 = -1.f;
#pragma unroll
    for (int e = 0; e < Ed; ++e) if (e != i1 && ex[e] > w2) { w2 = ex[e]; i2 = e; }
    float den = 1.f / (w1 + w2 + 1e-8f);
#pragma unroll
    for (int e = 0; e < Ed; ++e)
        g[e] = (e == i1) ? w1 * den : ((e == i2) ? w2 * den : 0.f);
}

__global__ __launch_bounds__(NTHREADS, 2)
void sasrec_fused_kernel(
    const int*   __restrict__ input_ids,
    const float* __restrict__ t_noise,   const float* __restrict__ i_noise,
    const float* __restrict__ item_table,const float* __restrict__ pos_table,
    const float* __restrict__ text_table,const float* __restrict__ img_table,
    const float* __restrict__ fc_text_w, const float* __restrict__ fc_text_b,
    const float* __restrict__ fc_img_w,  const float* __restrict__ fc_img_b,
    const float* __restrict__ ln_w,      const float* __restrict__ ln_b,
    const float* __restrict__ mu_t_w,    const float* __restrict__ mu_t_b,
    const float* __restrict__ sg_t_w,    const float* __restrict__ sg_t_b,
    const float* __restrict__ mu_i_w,    const float* __restrict__ mu_i_b,
    const float* __restrict__ sg_i_w,    const float* __restrict__ sg_i_b,
    const float* __restrict__ gate_w,    const float* __restrict__ gate_b,
    const float* __restrict__ texp_w,    const float* __restrict__ texp_b,
    const float* __restrict__ iexp_w,    const float* __restrict__ iexp_b,
    const float* __restrict__ fus_w,     const float* __restrict__ fus_b,
    const float* __restrict__ fus_ln_w,  const float* __restrict__ fus_ln_b,
    float*       __restrict__ out)
{
    extern __shared__ float sm[];
    float* sW  = sm + OFF_W;
    float* sA  = sm + OFF_A;
    float* sX  = sm + OFF_X;
    float* sY  = sm + OFF_Y;
    float* sgt = sm + OFF_GT;
    float* sgi = sm + OFF_GI;
    int*   sids = (int*)(sm + OFF_IDS);

    const int tid = threadIdx.x;
    const int tx  = tid & 15;
    const int ty  = tid >> 4;          // 0..15
    const int hlo = tx * 4;            // outputs hlo..hlo+3 and hlo+64..hlo+67
    const int n0  = blockIdx.x * TB;

    if (tid < TB) sids[tid] = input_ids[n0 + tid];
    __syncthreads();

    float acc[4][8];

    // ---------------- stage 1: text_emb = l2norm(text_table[ids] @ fc_text_w^T + b) -> sX
    {
#pragma unroll
        for (int p = 0; p < 4; ++p)
#pragma unroll
            for (int j = 0; j < 8; ++j) acc[p][j] = 0.f;
        for (int kc = 0; kc < DTd; kc += KC) {
            __syncthreads();
            gather_a_chunk(text_table, DTd, kc, sids, sA, tid);
            load_w_chunk(fc_text_w, DTd, kc, sW, tid);
            __syncthreads();
            gemm_chunk4(sA + ty * SA, sA + (ty + 16) * SA,
                        sA + (ty + 32) * SA, sA + (ty + 48) * SA, sW, tx, acc);
        }
        float4 blo = *reinterpret_cast<const float4*>(fc_text_b + hlo);
        float4 bhi = *reinterpret_cast<const float4*>(fc_text_b + hlo + 64);
        float bb[8] = {blo.x, blo.y, blo.z, blo.w, bhi.x, bhi.y, bhi.z, bhi.w};
#pragma unroll
        for (int p = 0; p < 4; ++p) {
            int t = ty + 16 * p;
            float ss = 0.f;
#pragma unroll
            for (int j = 0; j < 8; ++j) {
                acc[p][j] += bb[j];
                ss += acc[p][j] * acc[p][j];
            }
            ss = hreduce16(ss);
            float sc = 1.f / fmaxf(sqrtf(ss), 1e-12f);
            float4 olo = {acc[p][0] * sc, acc[p][1] * sc, acc[p][2] * sc, acc[p][3] * sc};
            float4 ohi = {acc[p][4] * sc, acc[p][5] * sc, acc[p][6] * sc, acc[p][7] * sc};
            *reinterpret_cast<float4*>(sX + t * SX + hlo)      = olo;
            *reinterpret_cast<float4*>(sX + t * SX + hlo + 64) = ohi;
        }
    }

    // ---------------- stage 2: img_emb -> sY ----------------
    {
#pragma unroll
        for (int p = 0; p < 4; ++p)
#pragma unroll
            for (int j = 0; j < 8; ++j) acc[p][j] = 0.f;
        for (int kc = 0; kc < DId; kc += KC) {
            __syncthreads();
            gather_a_chunk(img_table, DId, kc, sids, sA, tid);
            load_w_chunk(fc_img_w, DId, kc, sW, tid);
            __syncthreads();
            gemm_chunk4(sA + ty * SA, sA + (ty + 16) * SA,
                        sA + (ty + 32) * SA, sA + (ty + 48) * SA, sW, tx, acc);
        }
        float4 blo = *reinterpret_cast<const float4*>(fc_img_b + hlo);
        float4 bhi = *reinterpret_cast<const float4*>(fc_img_b + hlo + 64);
        float bb[8] = {blo.x, blo.y, blo.z, blo.w, bhi.x, bhi.y, bhi.z, bhi.w};
#pragma unroll
        for (int p = 0; p < 4; ++p) {
            int t = ty + 16 * p;
            float ss = 0.f;
#pragma unroll
            for (int j = 0; j < 8; ++j) {
                acc[p][j] += bb[j];
                ss += acc[p][j] * acc[p][j];
            }
            ss = hreduce16(ss);
            float sc = 1.f / fmaxf(sqrtf(ss), 1e-12f);
            float4 olo = {acc[p][0] * sc, acc[p][1] * sc, acc[p][2] * sc, acc[p][3] * sc};
            float4 ohi = {acc[p][4] * sc, acc[p][5] * sc, acc[p][6] * sc, acc[p][7] * sc};
            *reinterpret_cast<float4*>(sY + t * SX + hlo)      = olo;
            *reinterpret_cast<float4*>(sY + t * SX + hlo + 64) = ohi;
        }
    }

    // ---------------- stage 3: VAE reparam text (two half-token passes) -> sX ----------------
#pragma unroll 1
    for (int q = 0; q < 2; ++q) {
        const int tA = ty + 32 * q;
        float mu2[2][8], sg2[2][8];
#pragma unroll
        for (int p = 0; p < 2; ++p)
#pragma unroll
            for (int j = 0; j < 8; ++j) { mu2[p][j] = 0.f; sg2[p][j] = 0.f; }
        for (int kc = 0; kc < Hd; kc += KC) {
            __syncthreads();
            load_w_chunk(mu_t_w, Hd, kc, sW, tid);
            __syncthreads();
            gemm_chunk2(sX + tA * SX + kc, sX + (tA + 16) * SX + kc, sW, tx, mu2);
        }
        for (int kc = 0; kc < Hd; kc += KC) {
            __syncthreads();
            load_w_chunk(sg_t_w, Hd, kc, sW, tid);
            __syncthreads();
            gemm_chunk2(sX + tA * SX + kc, sX + (tA + 16) * SX + kc, sW, tx, sg2);
        }
        float4 mblo = *reinterpret_cast<const float4*>(mu_t_b + hlo);
        float4 mbhi = *reinterpret_cast<const float4*>(mu_t_b + hlo + 64);
        float4 sblo = *reinterpret_cast<const float4*>(sg_t_b + hlo);
        float4 sbhi = *reinterpret_cast<const float4*>(sg_t_b + hlo + 64);
        float mb[8] = {mblo.x, mblo.y, mblo.z, mblo.w, mbhi.x, mbhi.y, mbhi.z, mbhi.w};
        float sb[8] = {sblo.x, sblo.y, sblo.z, sblo.w, sbhi.x, sbhi.y, sbhi.z, sbhi.w};
#pragma unroll
        for (int p = 0; p < 2; ++p) {
            int t = tA + 16 * p;
            const float* np = t_noise + (long)(n0 + t) * Hd;
            float4 nlo = *reinterpret_cast<const float4*>(np + hlo);
            float4 nhi = *reinterpret_cast<const float4*>(np + hlo + 64);
            float nn[8] = {nlo.x, nlo.y, nlo.z, nlo.w, nhi.x, nhi.y, nhi.z, nhi.w};
            float z[8];
#pragma unroll
            for (int j = 0; j < 8; ++j)
                z[j] = mu2[p][j] + mb[j] + __expf(sg2[p][j] + sb[j]) * nn[j];
            float4 zlo = {z[0], z[1], z[2], z[3]};
            float4 zhi = {z[4], z[5], z[6], z[7]};
            *reinterpret_cast<float4*>(sX + t * SX + hlo)      = zlo;
            *reinterpret_cast<float4*>(sX + t * SX + hlo + 64) = zhi;
        }
    }

    // ---------------- stage 4: VAE reparam img (two half-token passes) -> sY ----------------
#pragma unroll 1
    for (int q = 0; q < 2; ++q) {
        const int tA = ty + 32 * q;
        float mu2[2][8], sg2[2][8];
#pragma unroll
        for (int p = 0; p < 2; ++p)
#pragma unroll
            for (int j = 0; j < 8; ++j) { mu2[p][j] = 0.f; sg2[p][j] = 0.f; }
        for (int kc = 0; kc < Hd; kc += KC) {
            __syncthreads();
            load_w_chunk(mu_i_w, Hd, kc, sW, tid);
            __syncthreads();
            gemm_chunk2(sY + tA * SX + kc, sY + (tA + 16) * SX + kc, sW, tx, mu2);
        }
        for (int kc = 0; kc < Hd; kc += KC) {
            __syncthreads();
            load_w_chunk(sg_i_w, Hd, kc, sW, tid);
            __syncthreads();
            gemm_chunk2(sY + tA * SX + kc, sY + (tA + 16) * SX + kc, sW, tx, sg2);
        }
        float4 mblo = *reinterpret_cast<const float4*>(mu_i_b + hlo);
        float4 mbhi = *reinterpret_cast<const float4*>(mu_i_b + hlo + 64);
        float4 sblo = *reinterpret_cast<const float4*>(sg_i_b + hlo);
        float4 sbhi = *reinterpret_cast<const float4*>(sg_i_b + hlo + 64);
        float mb[8] = {mblo.x, mblo.y, mblo.z, mblo.w, mbhi.x, mbhi.y, mbhi.z, mbhi.w};
        float sb[8] = {sblo.x, sblo.y, sblo.z, sblo.w, sbhi.x, sbhi.y, sbhi.z, sbhi.w};
#pragma unroll
        for (int p = 0; p < 2; ++p) {
            int t = tA + 16 * p;
            const float* np = i_noise + (long)(n0 + t) * Hd;
            float4 nlo = *reinterpret_cast<const float4*>(np + hlo);
            float4 nhi = *reinterpret_cast<const float4*>(np + hlo + 64);
            float nn[8] = {nlo.x, nlo.y, nlo.z, nlo.w, nhi.x, nhi.y, nhi.z, nhi.w};
            float z[8];
#pragma unroll
            for (int j = 0; j < 8; ++j)
                z[j] = mu2[p][j] + mb[j] + __expf(sg2[p][j] + sb[j]) * nn[j];
            float4 zlo = {z[0], z[1], z[2], z[3]};
            float4 zhi = {z[4], z[5], z[6], z[7]};
            *reinterpret_cast<float4*>(sY + t * SX + hlo)      = zlo;
            *reinterpret_cast<float4*>(sY + t * SX + hlo + 64) = zhi;
        }
    }

    // ---------------- stage 5: gating (both modalities) ----------------
    __syncthreads();
    {
        int t  = tid >> 2;            // 0..63
        int e0 = (tid & 3) * 2;       // each thread: experts e0, e0+1
#pragma unroll
        for (int qe = 0; qe < 2; ++qe) {
            int e = e0 + qe;
            const float* gw = gate_w + e * Hd;
            float dt = 0.f, di = 0.f;
#pragma unroll 8
            for (int k4 = 0; k4 < Hd; k4 += 4) {
                float4 w = *reinterpret_cast<const float4*>(gw + k4);
                float4 x = *reinterpret_cast<const float4*>(sX + t * SX + k4);
                float4 y = *reinterpret_cast<const float4*>(sY + t * SX + k4);
                dt = fmaf(x.x, w.x, fmaf(x.y, w.y, fmaf(x.z, w.z, fmaf(x.w, w.w, dt))));
                di = fmaf(y.x, w.x, fmaf(y.y, w.y, fmaf(y.z, w.z, fmaf(y.w, w.w, di))));
            }
            sgt[t * Ed + e] = dt + gate_b[e];
            sgi[t * Ed + e] = di + gate_b[e];
        }
    }
    __syncthreads();
    if (tid < TB) {
        route8(sgt + tid * Ed);
        route8(sgi + tid * Ed);
    }
    __syncthreads();

    // ---------------- stage 6: text experts (top-2 sparse, gate folded into A) -> sX ----------------
    {
        float outv[4][8];
#pragma unroll
        for (int p = 0; p < 4; ++p) {
            int t = ty + 16 * p;
#pragma unroll
            for (int j = 0; j < 8; ++j) outv[p][j] = 0.f;
#pragma unroll
            for (int e = 0; e < Ed; ++e) {
                float g = sgt[t * Ed + e];
                if (g != 0.f) {
                    const float* bp = texp_b + e * Hd;
                    float4 blo = *reinterpret_cast<const float4*>(bp + hlo);
                    float4 bhi = *reinterpret_cast<const float4*>(bp + hlo + 64);
                    float bb[8] = {blo.x, blo.y, blo.z, blo.w, bhi.x, bhi.y, bhi.z, bhi.w};
#pragma unroll
                    for (int j = 0; j < 8; ++j)
                        outv[p][j] = fmaf(g, bb[j], outv[p][j]);
                }
            }
        }
#pragma unroll 1
        for (int e = 0; e < Ed; ++e) {
            const float* We = texp_w + (long)e * Hd * Hd;
#pragma unroll 1
            for (int kc = 0; kc < Hd; kc += KC) {
                __syncthreads();
                load_w_chunk(We, Hd, kc, sW, tid);
                __syncthreads();
#pragma unroll
                for (int p = 0; p < 4; ++p) {
                    float g = sgt[(ty + 16 * p) * Ed + e];
                    if (g != 0.f)
                        gemm_gated(sX + (ty + 16 * p) * SX + kc, g, sW, tx, outv[p]);
                }
            }
        }
        __syncthreads();
#pragma unroll
        for (int p = 0; p < 4; ++p) {
            int t = ty + 16 * p;
            float4 olo = {outv[p][0], outv[p][1], outv[p][2], outv[p][3]};
            float4 ohi = {outv[p][4], outv[p][5], outv[p][6], outv[p][7]};
            *reinterpret_cast<float4*>(sX + t * SX + hlo)      = olo;
            *reinterpret_cast<float4*>(sX + t * SX + hlo + 64) = ohi;
        }
    }

    // ---------------- stage 7: img experts -> sY ----------------
    {
        float outv[4][8];
#pragma unroll
        for (int p = 0; p < 4; ++p) {
            int t = ty + 16 * p;
#pragma unroll
            for (int j = 0; j < 8; ++j) outv[p][j] = 0.f;
#pragma unroll
            for (int e = 0; e < Ed; ++e) {
                float g = sgi[t * Ed + e];
                if (g != 0.f) {
                    const float* bp = iexp_b + e * Hd;
                    float4 blo = *reinterpret_cast<const float4*>(bp + hlo);
                    float4 bhi = *reinterpret_cast<const float4*>(bp + hlo + 64);
                    float bb[8] = {blo.x, blo.y, blo.z, blo.w, bhi.x, bhi.y, bhi.z, bhi.w};
#pragma unroll
                    for (int j = 0; j < 8; ++j)
                        outv[p][j] = fmaf(g, bb[j], outv[p][j]);
                }
            }
        }
#pragma unroll 1
        for (int e = 0; e < Ed; ++e) {
            const float* We = iexp_w + (long)e * Hd * Hd;
#pragma unroll 1
            for (int kc = 0; kc < Hd; kc += KC) {
                __syncthreads();
                load_w_chunk(We, Hd, kc, sW, tid);
                __syncthreads();
#pragma unroll
                for (int p = 0; p < 4; ++p) {
                    float g = sgi[(ty + 16 * p) * Ed + e];
                    if (g != 0.f)
                        gemm_gated(sY + (ty + 16 * p) * SX + kc, g, sW, tx, outv[p]);
                }
            }
        }
        __syncthreads();
#pragma unroll
        for (int p = 0; p < 4; ++p) {
            int t = ty + 16 * p;
            float4 olo = {outv[p][0], outv[p][1], outv[p][2], outv[p][3]};
            float4 ohi = {outv[p][4], outv[p][5], outv[p][6], outv[p][7]};
            *reinterpret_cast<float4*>(sY + t * SX + hlo)      = olo;
            *reinterpret_cast<float4*>(sY + t * SX + hlo + 64) = ohi;
        }
    }

    // ---------------- stage 8: fusion + recomputed seq_emb ----------------
    {
#pragma unroll
        for (int p = 0; p < 4; ++p)
#pragma unroll
            for (int j = 0; j < 8; ++j) acc[p][j] = 0.f;
        for (int kc = 0; kc < 2 * Hd; kc += KC) {
            __syncthreads();
            load_w_chunk(fus_w, 2 * Hd, kc, sW, tid);
            __syncthreads();
            const float* base = (kc < Hd) ? sX : sY;
            int ko = (kc < Hd) ? kc : (kc - Hd);
            gemm_chunk4(base + ty * SX + ko, base + (ty + 16) * SX + ko,
                        base + (ty + 32) * SX + ko, base + (ty + 48) * SX + ko,
                        sW, tx, acc);
        }
        float4 fblo = *reinterpret_cast<const float4*>(fus_b + hlo);
        float4 fbhi = *reinterpret_cast<const float4*>(fus_b + hlo + 64);
        float fb[8] = {fblo.x, fblo.y, fblo.z, fblo.w, fbhi.x, fbhi.y, fbhi.z, fbhi.w};
        float4 fwlo = *reinterpret_cast<const float4*>(fus_ln_w + hlo);
        float4 fwhi = *reinterpret_cast<const float4*>(fus_ln_w + hlo + 64);
        float flw[8] = {fwlo.x, fwlo.y, fwlo.z, fwlo.w, fwhi.x, fwhi.y, fwhi.z, fwhi.w};
        float4 fllo = *reinterpret_cast<const float4*>(fus_ln_b + hlo);
        float4 flhi = *reinterpret_cast<const float4*>(fus_ln_b + hlo + 64);
        float flb[8] = {fllo.x, fllo.y, fllo.z, fllo.w, flhi.x, flhi.y, flhi.z, flhi.w};
        float4 lwlo = *reinterpret_cast<const float4*>(ln_w + hlo);
        float4 lwhi = *reinterpret_cast<const float4*>(ln_w + hlo + 64);
        float lw[8] = {lwlo.x, lwlo.y, lwlo.z, lwlo.w, lwhi.x, lwhi.y, lwhi.z, lwhi.w};
        float4 lblo = *reinterpret_cast<const float4*>(ln_b + hlo);
        float4 lbhi = *reinterpret_cast<const float4*>(ln_b + hlo + 64);
        float lb[8] = {lblo.x, lblo.y, lblo.z, lblo.w, lbhi.x, lbhi.y, lbhi.z, lbhi.w};
#pragma unroll
        for (int p = 0; p < 4; ++p) {
            int t = ty + 16 * p;
            int n = n0 + t;
            // fusion LN
            float s = 0.f, sq = 0.f;
#pragma unroll
            for (int j = 0; j < 8; ++j) {
                acc[p][j] += fb[j];
                s += acc[p][j]; sq += acc[p][j] * acc[p][j];
            }
            s  = hreduce16(s);
            sq = hreduce16(sq);
            float mean = s * (1.f / Hd);
            float var  = sq * (1.f / Hd) - mean * mean;
            float inv  = rsqrtf(var + 1e-5f);
            // recompute seq_emb = LN(item + pos)
            int id  = sids[t];
            int pos = n % Ld;
            const float* ip = item_table + (long)id * Hd;
            const float* pp = pos_table + pos * Hd;
            float4 ilo = *reinterpret_cast<const float4*>(ip + hlo);
            float4 ihi = *reinterpret_cast<const float4*>(ip + hlo + 64);
            float4 plo = *reinterpret_cast<const float4*>(pp + hlo);
            float4 phi = *reinterpret_cast<const float4*>(pp + hlo + 64);
            float v[8] = {ilo.x + plo.x, ilo.y + plo.y, ilo.z + plo.z, ilo.w + plo.w,
                          ihi.x + phi.x, ihi.y + phi.y, ihi.z + phi.z, ihi.w + phi.w};
            float s2 = 0.f, sq2 = 0.f;
#pragma unroll
            for (int j = 0; j < 8; ++j) { s2 += v[j]; sq2 += v[j] * v[j]; }
            s2  = hreduce16(s2);
            sq2 = hreduce16(sq2);
            float mean2 = s2 * (1.f / Hd);
            float var2  = sq2 * (1.f / Hd) - mean2 * mean2;
            float inv2  = rsqrtf(var2 + 1e-12f);
            float r[8];
#pragma unroll
            for (int j = 0; j < 8; ++j) {
                float y   = (acc[p][j] - mean) * inv * flw[j] + flb[j];
                float seq = (v[j] - mean2) * inv2 * lw[j] + lb[j];
                r[j] = fmaxf(y, 0.f) + seq;
            }
            float4 rlo = {r[0], r[1], r[2], r[3]};
            float4 rhi = {r[4], r[5], r[6], r[7]};
            *reinterpret_cast<float4*>(out + (long)n * Hd + hlo)      = rlo;
            *reinterpret_cast<float4*>(out + (long)n * Hd + hlo + 64) = rhi;
        }
    }
}

extern "C" void kernel_launch(void* const* d_in, const int* in_sizes, int n_in,
                              void* d_out, int out_size) {
    (void)in_sizes; (void)n_in; (void)out_size;
    const int*   input_ids  = (const int*)  d_in[0];
    const float* t_noise    = (const float*)d_in[1];
    const float* i_noise    = (const float*)d_in[2];
    const float* item_table = (const float*)d_in[3];
    const float* pos_table  = (const float*)d_in[4];
    const float* text_table = (const float*)d_in[5];
    const float* img_table  = (const float*)d_in[6];
    const float* fc_text_w  = (const float*)d_in[7];
    const float* fc_text_b  = (const float*)d_in[8];
    const float* fc_img_w   = (const float*)d_in[9];
    const float* fc_img_b   = (const float*)d_in[10];
    const float* ln_w       = (const float*)d_in[11];
    const float* ln_b       = (const float*)d_in[12];
    const float* mu_t_w     = (const float*)d_in[13];
    const float* mu_t_b     = (const float*)d_in[14];
    const float* sg_t_w     = (const float*)d_in[15];
    const float* sg_t_b     = (const float*)d_in[16];
    const float* mu_i_w     = (const float*)d_in[17];
    const float* mu_i_b     = (const float*)d_in[18];
    const float* sg_i_w     = (const float*)d_in[19];
    const float* sg_i_b     = (const float*)d_in[20];
    const float* gate_w     = (const float*)d_in[21];
    const float* gate_b     = (const float*)d_in[22];
    const float* texp_w     = (const float*)d_in[23];
    const float* texp_b     = (const float*)d_in[24];
    const float* iexp_w     = (const float*)d_in[25];
    const float* iexp_b     = (const float*)d_in[26];
    const float* fus_w      = (const float*)d_in[27];
    const float* fus_b      = (const float*)d_in[28];
    const float* fus_ln_w   = (const float*)d_in[29];
    const float* fus_ln_b   = (const float*)d_in[30];

    size_t smem = SMEM_FLOATS * sizeof(float);
    cudaFuncSetAttribute(sasrec_fused_kernel,
                         cudaFuncAttributeMaxDynamicSharedMemorySize, (int)smem);

    sasrec_fused_kernel<<<NTOK / TB, NTHREADS, smem>>>(
        input_ids, t_noise, i_noise, item_table, pos_table, text_table, img_table,
        fc_text_w, fc_text_b, fc_img_w, fc_img_b, ln_w, ln_b,
        mu_t_w, mu_t_b, sg_t_w, sg_t_b, mu_i_w, mu_i_b, sg_i_w, sg_i_b,
        gate_w, gate_b, texp_w, texp_b, iexp_w, iexp_b,
        fus_w, fus_b, fus_ln_w, fus_ln_b,
        (float*)d_out);
}